// round 10
// baseline (speedup 1.0000x reference)
#include <cuda_runtime.h>
#include <cuda_fp16.h>
#include <math.h>
#include <stdint.h>

#define E_EDGES 800000
#define NN      50000
typedef unsigned long long ull;

__device__ int    g_idx64;
__device__ float  g_agg[(size_t)NN * 64];
__device__ float  g_P[(size_t)50048 * 512];   // [node][ P_src(256) | P_dst(256) ]
__device__ __half g_B1e[2 * 256 * 72];        // ef-part W1: [hi|lo][256 n][72 kpad]
__device__ __half g_BP[2 * 512 * 72];         // P-prep W1:  [hi|lo][512 n][72 kpad]
__device__ __half g_W2[2 * 2 * 64 * 136];     // [gate][hi|lo][64 n][136 kpad]
__device__ __half g_Wn1[2 * 128 * 136];       // node W1: [hi|lo][128 n][136 kpad]
__device__ __half g_Wn2[2 * 64 * 136];        // node W2: [hi|lo][64 n][136 kpad]

// ---------------- helpers ----------------------------------------------------
__device__ __forceinline__ uint32_t smem_u32(const void* p) {
    uint32_t a;
    asm("{ .reg .u64 t; cvta.to.shared.u64 t, %1; cvt.u32.u64 %0, t; }" : "=r"(a) : "l"(p));
    return a;
}
__device__ __forceinline__ void ldsm4(uint32_t* r, uint32_t addr) {
    asm volatile("ldmatrix.sync.aligned.m8n8.x4.shared.b16 {%0,%1,%2,%3}, [%4];"
                 : "=r"(r[0]), "=r"(r[1]), "=r"(r[2]), "=r"(r[3]) : "r"(addr));
}
__device__ __forceinline__ void mma16816(float* c, const uint32_t* a, uint32_t b0, uint32_t b1) {
    asm volatile("mma.sync.aligned.m16n8k16.row.col.f32.f16.f16.f32 "
                 "{%0,%1,%2,%3}, {%4,%5,%6,%7}, {%8,%9}, {%0,%1,%2,%3};"
                 : "+f"(c[0]), "+f"(c[1]), "+f"(c[2]), "+f"(c[3])
                 : "r"(a[0]), "r"(a[1]), "r"(a[2]), "r"(a[3]), "r"(b0), "r"(b1));
}
__device__ __forceinline__ void cpa16(uint32_t dst, const void* src) {
    asm volatile("cp.async.cg.shared.global [%0], [%1], 16;" :: "r"(dst), "l"(src));
}
#define CP_COMMIT() asm volatile("cp.async.commit_group;" ::: "memory")
#define CP_WAIT0()  asm volatile("cp.async.wait_group 0;" ::: "memory")
#define CP_WAIT1()  asm volatile("cp.async.wait_group 1;" ::: "memory")
__device__ __forceinline__ void red2(float* p, float x, float y) {
    asm volatile("red.global.add.v2.f32 [%0], {%1,%2};" :: "l"(p), "f"(x), "f"(y) : "memory");
}
__device__ __forceinline__ uint32_t packh2(float x, float y) {
    __half2 h = __floats2half2_rn(x, y);
    return *(uint32_t*)&h;
}
__device__ __forceinline__ float2 unpackh2(uint32_t u) {
    return __half22float2(*(__half2*)&u);
}

// ---------------------------------------------------------------------------
// prep_all: fused zero+detect+all weight preps (one launch).
// blocks: [0,3125) zero agg | 3125 detect | [3126,3254) b1e | [3254,3382) w2
//         [3382,3638) bp | [3638,3766) wn1 | [3766,3830) wn2
// ---------------------------------------------------------------------------
__global__ void prep_all(const unsigned int* __restrict__ raw,
                         const float* __restrict__ We1, const float* __restrict__ Wa1,
                         const float* __restrict__ We2, const float* __restrict__ Wa2,
                         const float* __restrict__ Wn1, const float* __restrict__ Wn2)
{
    const int b = blockIdx.x, t = threadIdx.x;
    if (b < 3125) {
        ((float4*)g_agg)[b * 256 + t] = make_float4(0.f, 0.f, 0.f, 0.f);
    } else if (b == 3125) {
        __shared__ int any;
        if (t == 0) any = 0;
        __syncthreads();
        int f = 0;
        for (int i = t; i < 2048; i += blockDim.x)
            if (raw[2 * i + 1] != 0u) f = 1;
        if (f) atomicExch(&any, 1);
        __syncthreads();
        if (t == 0) g_idx64 = (any == 0) ? 1 : 0;
    } else if (b < 3254) {
        int gi = (b - 3126) * 256 + t;              // 32768
        int p = gi >> 14, r = gi & 16383;
        int n = r >> 6, kk = r & 63;
        int k = 128 + kk;
        float w = (n < 128) ? We1[k * 128 + n] : Wa1[k * 128 + (n - 128)];
        __half hi = __float2half_rn(w);
        __half v = (p == 0) ? hi : __float2half_rn(w - __half2float(hi));
        g_B1e[(p * 256 + n) * 72 + kk] = v;
    } else if (b < 3382) {
        int gi = (b - 3254) * 256 + t;              // 32768
        int g = gi >> 14, p = (gi >> 13) & 1;
        int r = gi & 8191, n = r >> 7, k = r & 127;
        const float* W = g ? Wa2 : We2;
        float w = W[k * 64 + n];
        __half hi = __float2half_rn(w);
        __half v = (p == 0) ? hi : __float2half_rn(w - __half2float(hi));
        g_W2[((g * 2 + p) * 64 + n) * 136 + k] = v;
    } else if (b < 3638) {
        int gi = (b - 3382) * 256 + t;              // 65536
        int p = gi >> 15, r = gi & 32767;
        int nIdx = r >> 6, kk = r & 63;
        int part = nIdx >> 8, c = nIdx & 255;
        int k = part * 64 + kk;
        float w = (c < 128) ? We1[k * 128 + c] : Wa1[k * 128 + (c - 128)];
        __half hi = __float2half_rn(w);
        __half v = (p == 0) ? hi : __float2half_rn(w - __half2float(hi));
        g_BP[(p * 512 + nIdx) * 72 + kk] = v;
    } else if (b < 3766) {
        int gi = (b - 3638) * 256 + t;              // 32768
        int p = gi >> 14, r = gi & 16383;
        int n = r >> 7, k = r & 127;
        float w = Wn1[k * 128 + n];
        __half hi = __float2half_rn(w);
        __half v = (p == 0) ? hi : __float2half_rn(w - __half2float(hi));
        g_Wn1[(p * 128 + n) * 136 + k] = v;
    } else {
        int gi = (b - 3766) * 256 + t;              // 16384
        int p = gi >> 13, r = gi & 8191;
        int n = r >> 7, k = r & 127;
        float w = Wn2[k * 64 + n];
        __half hi = __float2half_rn(w);
        __half v = (p == 0) ? hi : __float2half_rn(w - __half2float(hi));
        g_Wn2[(p * 64 + n) * 136 + k] = v;
    }
}

// ---------------------------------------------------------------------------
// prep_P: P[n][512] = nf[n] @ [W_src | W_dst], split-fp16 3-term HMMA.
// ---------------------------------------------------------------------------
#define PREP_SMEM 184320
__global__ __launch_bounds__(256, 1) void prep_P_kernel(const float* __restrict__ nf)
{
    extern __shared__ char smc[];
    const uint32_t smb = smem_u32(smc);
    const int tid = threadIdx.x, wid = tid >> 5, lane = tid & 31;
    const int m0 = blockIdx.x * 128;

    #pragma unroll
    for (int i = 0; i < 36; i++)
        cpa16(smb + 36864 + (tid + 256 * i) * 16, (const char*)g_BP + (tid + 256 * i) * 16);
    CP_COMMIT();

    {
        const int m = tid >> 1, h = tid & 1;
        const int node = m0 + m;
        const float* row = nf + (size_t)node * 64;
        #pragma unroll
        for (int it = 0; it < 8; it++) {
            int q = h * 8 + it;
            float4 v = (node < NN) ? ((const float4*)row)[q] : make_float4(0.f, 0.f, 0.f, 0.f);
            uint32_t h0 = packh2(v.x, v.y), h1 = packh2(v.z, v.w);
            float2 f0 = unpackh2(h0), f1 = unpackh2(h1);
            uint32_t l0 = packh2(v.x - f0.x, v.y - f0.y), l1 = packh2(v.z - f1.x, v.w - f1.y);
            *(uint2*)(smc + 0     + m * 144 + q * 8) = make_uint2(h0, h1);
            *(uint2*)(smc + 18432 + m * 144 + q * 8) = make_uint2(l0, l1);
        }
    }
    CP_WAIT0();
    __syncthreads();

    const int wr = wid * 16;
    const uint32_t aH = smb + (uint32_t)((wr + (lane & 15)) * 144 + ((lane >> 4) * 8) * 2);
    const uint32_t aL = aH + 18432;
    const uint32_t bln = (uint32_t)((((lane >> 4) << 3) + (lane & 7)) * 144 + (((lane >> 3) & 1) ? 16 : 0));
    const int r0 = wr + (lane >> 2);
    const int ec = 2 * (lane & 3);

    #pragma unroll
    for (int p = 0; p < 2; p++) {
        float acc[128];
        #pragma unroll
        for (int i = 0; i < 128; i++) acc[i] = 0.f;
        const uint32_t bH = smb + 36864  + (uint32_t)(p * 36864) + bln;
        const uint32_t bL = bH + 73728;
        #pragma unroll
        for (int ks = 0; ks < 4; ks++) {
            uint32_t ah[4], al[4];
            ldsm4(ah, aH + ks * 32);
            ldsm4(al, aL + ks * 32);
            #pragma unroll
            for (int j2 = 0; j2 < 16; j2++) {
                uint32_t bh[4], bl[4];
                ldsm4(bh, bH + j2 * 2304 + ks * 32);
                ldsm4(bl, bL + j2 * 2304 + ks * 32);
                mma16816(&acc[(2*j2+0)*4], ah, bh[0], bh[1]); mma16816(&acc[(2*j2+1)*4], ah, bh[2], bh[3]);
                mma16816(&acc[(2*j2+0)*4], al, bh[0], bh[1]); mma16816(&acc[(2*j2+1)*4], al, bh[2], bh[3]);
                mma16816(&acc[(2*j2+0)*4], ah, bl[0], bl[1]); mma16816(&acc[(2*j2+1)*4], ah, bl[2], bl[3]);
            }
        }
        #pragma unroll
        for (int j8 = 0; j8 < 32; j8++) {
            int cb = p * 256 + 8 * j8 + ec;
            *(float2*)(g_P + (size_t)(m0 + r0) * 512 + cb)     = make_float2(acc[4*j8+0], acc[4*j8+1]);
            *(float2*)(g_P + (size_t)(m0 + r0 + 8) * 512 + cb) = make_float2(acc[4*j8+2], acc[4*j8+3]);
        }
    }
}

// ---------------------------------------------------------------------------
// Edge kernel, occ-3, double-buffered B1, Psum folded into epilogue-1.
//  GEMM1:  A1H @0 (9216), A1L @9216 (9216), B1A @18432 (18432), B1B @36864 (18432)
//  GEMM2:  W2 @0 (69632: e-gate 34816 | a-gate 34816)   [A1/B1 dead]
//  misc @69632 (2048) -> 71680 ; 3 CTAs x 71680 = 215040 <= 227KB
// ---------------------------------------------------------------------------
#define OFF_A1H  0
#define OFF_A1L  9216
#define OFF_B1A  18432
#define OFF_B1B  36864
#define OFF_MISC 69632
#define EDGE_SMEM 71680

__global__ __launch_bounds__(128, 3) void edge_kernel(
    const float* __restrict__ ef,
    const int* __restrict__ rawsrc, const int* __restrict__ rawdst,
    const float* __restrict__ be1, const float* __restrict__ ba1,
    const float* __restrict__ be2, const float* __restrict__ ba2,
    float* __restrict__ ef_out)
{
    extern __shared__ char smc[];
    const uint32_t smb = smem_u32(smc);
    const int tid = threadIdx.x, wid = tid >> 5, lane = tid & 31;
    const int e0 = blockIdx.x * 64;

    int*   sSrc  = (int*)(smc + OFF_MISC);
    int*   sDst  = (int*)(smc + OFF_MISC + 256);
    float* sBias = (float*)(smc + OFF_MISC + 512);
    float* sB2b  = (float*)(smc + OFF_MISC + 1536);

    // B1 stages 0,1 into the two buffers (groups 0,1)
    #pragma unroll
    for (int i = 0; i < 9; i++)
        cpa16(smb + OFF_B1A + (tid + 128 * i) * 16, (const char*)g_B1e + (tid + 128 * i) * 16);
    CP_COMMIT();
    #pragma unroll
    for (int i = 0; i < 9; i++)
        cpa16(smb + OFF_B1B + (tid + 128 * i) * 16, (const char*)g_B1e + 18432 + (tid + 128 * i) * 16);
    CP_COMMIT();

    const int is64 = g_idx64;
    if (tid < 64) sSrc[tid] = is64 ? rawsrc[2 * (e0 + tid)] : rawsrc[e0 + tid];
    else { int m = tid - 64; sDst[m] = is64 ? rawdst[2 * (e0 + m)] : rawdst[e0 + m]; }
    if (tid < 64)
        ((float4*)sBias)[tid] = (tid < 32) ? ((const float4*)be1)[tid] : ((const float4*)ba1)[tid - 32];
    else if (tid < 96)
        ((float4*)sB2b)[tid - 64] = (tid < 80) ? ((const float4*)be2)[tid - 64] : ((const float4*)ba2)[tid - 80];

    // gather ef rows, split hi/lo
    {
        const int m = tid >> 1, h = tid & 1;
        const float* row = ef + (size_t)(e0 + m) * 64;
        #pragma unroll
        for (int it = 0; it < 8; it++) {
            int q = h * 8 + it;
            float4 v = ((const float4*)row)[q];
            uint32_t h0 = packh2(v.x, v.y), h1 = packh2(v.z, v.w);
            float2 f0 = unpackh2(h0), f1 = unpackh2(h1);
            uint32_t l0 = packh2(v.x - f0.x, v.y - f0.y), l1 = packh2(v.z - f1.x, v.w - f1.y);
            *(uint2*)(smc + OFF_A1H + m * 144 + q * 8) = make_uint2(h0, h1);
            *(uint2*)(smc + OFF_A1L + m * 144 + q * 8) = make_uint2(l0, l1);
        }
    }

    const int wr = wid * 16;
    const uint32_t aH = smb + OFF_A1H + (uint32_t)((wr + (lane & 15)) * 144 + ((lane >> 4) * 8) * 2);
    const uint32_t aL = aH + 9216;
    const uint32_t bln = (uint32_t)((((lane >> 4) << 3) + (lane & 7)) * 144 + (((lane >> 3) & 1) ? 16 : 0));

    float acc[128];
    #pragma unroll
    for (int i = 0; i < 128; i++) acc[i] = 0.f;

    // ---- GEMM1, 4 stages {Wh n0, Wh n1, Wl n0, Wl n1}, double-buffered ----
    #pragma unroll
    for (int s = 0; s < 4; s++) {
        if (s < 3) { CP_WAIT1(); } else { CP_WAIT0(); }
        __syncthreads();
        const uint32_t bB = smb + ((s & 1) ? OFF_B1B : OFF_B1A) + bln;
        const int jbase = (s & 1) * 8;
        const bool p1 = (s < 2);
        #pragma unroll
        for (int ks = 0; ks < 4; ks++) {
            uint32_t ah[4], al[4];
            ldsm4(ah, aH + ks * 32);
            if (p1) ldsm4(al, aL + ks * 32);
            #pragma unroll
            for (int j2l = 0; j2l < 8; j2l++) {
                uint32_t bh[4];
                ldsm4(bh, bB + j2l * 2304 + ks * 32);
                int j2 = jbase + j2l;
                mma16816(&acc[(2*j2+0)*4], ah, bh[0], bh[1]);
                mma16816(&acc[(2*j2+1)*4], ah, bh[2], bh[3]);
                if (p1) {
                    mma16816(&acc[(2*j2+0)*4], al, bh[0], bh[1]);
                    mma16816(&acc[(2*j2+1)*4], al, bh[2], bh[3]);
                }
            }
        }
        __syncthreads();
        if (s < 2) {
            #pragma unroll
            for (int i = 0; i < 9; i++)
                cpa16(smb + ((s & 1) ? OFF_B1B : OFF_B1A) + (tid + 128 * i) * 16,
                      (const char*)g_B1e + (s + 2) * 18432 + (tid + 128 * i) * 16);
            CP_COMMIT();
        }
    }
    // A1/B1 dead. Issue W2 copies now (overlap with epilogue-1).
    #pragma unroll
    for (int i = 0; i < 17; i++)
        cpa16(smb + (tid + 128 * i) * 16, (const char*)g_W2 + (tid + 128 * i) * 16);
    CP_COMMIT();
    #pragma unroll
    for (int i = 0; i < 17; i++)
        cpa16(smb + 34816 + (tid + 128 * i) * 16, (const char*)g_W2 + 34816 + (tid + 128 * i) * 16);
    CP_COMMIT();

    // ---- epilogue 1: H = relu(acc + P_src + P_dst + bias), P direct from gmem ----
    uint32_t hH[64], hL[64];
    {
        const int r0 = wr + (lane >> 2), r1 = r0 + 8;
        const int ec = 2 * (lane & 3);
        const float* ps0 = g_P + (size_t)sSrc[r0] * 512;
        const float* pd0 = g_P + (size_t)sDst[r0] * 512 + 256;
        const float* ps1 = g_P + (size_t)sSrc[r1] * 512;
        const float* pd1 = g_P + (size_t)sDst[r1] * 512 + 256;
        #pragma unroll
        for (int j8 = 0; j8 < 32; j8++) {
            int cb = 8 * j8 + ec;
            float2 a0 = *(const float2*)(ps0 + cb);
            float2 b0 = *(const float2*)(pd0 + cb);
            float2 a1 = *(const float2*)(ps1 + cb);
            float2 b1 = *(const float2*)(pd1 + cb);
            float bb0 = sBias[cb], bb1 = sBias[cb + 1];
            float v0 = fmaxf(acc[4*j8+0] + a0.x + b0.x + bb0, 0.f);
            float v1 = fmaxf(acc[4*j8+1] + a0.y + b0.y + bb1, 0.f);
            float v2 = fmaxf(acc[4*j8+2] + a1.x + b1.x + bb0, 0.f);
            float v3 = fmaxf(acc[4*j8+3] + a1.y + b1.y + bb1, 0.f);
            uint32_t h01 = packh2(v0, v1);
            float2 f01 = unpackh2(h01);
            uint32_t l01 = packh2(v0 - f01.x, v1 - f01.y);
            uint32_t h23 = packh2(v2, v3);
            float2 f23 = unpackh2(h23);
            uint32_t l23 = packh2(v2 - f23.x, v3 - f23.y);
            hH[2*j8]   = h01; hL[2*j8]   = l01;
            hH[2*j8+1] = h23; hL[2*j8+1] = l23;
        }
    }

    // ---- GEMM2: hf=0 (gate e, W2 part1), then hf=1 (gate a, part2) ----
    const uint32_t w2ln = (uint32_t)((((lane >> 4) << 3) + (lane & 7)) * 272 + (((lane >> 3) & 1) ? 16 : 0));
    float acc2[64];
    #pragma unroll
    for (int i = 0; i < 64; i++) acc2[i] = 0.f;

    #pragma unroll
    for (int hf = 0; hf < 2; hf++) {
        if (hf == 0) { CP_WAIT1(); } else { CP_WAIT0(); }
        __syncthreads();
        const uint32_t wb = smb + (uint32_t)(hf * 34816) + w2ln;
        #pragma unroll
        for (int kc = 0; kc < 8; kc++) {
            int jb = 2 * (hf * 16 + 2 * kc);
            uint32_t ah[4] = { hH[jb], hH[jb+1], hH[jb+2], hH[jb+3] };
            uint32_t al[4] = { hL[jb], hL[jb+1], hL[jb+2], hL[jb+3] };
            #pragma unroll
            for (int j2 = 0; j2 < 4; j2++) {
                uint32_t bh[4], bl[4];
                ldsm4(bh, wb + j2 * 4352 + kc * 32);
                ldsm4(bl, wb + 17408 + j2 * 4352 + kc * 32);
                float* c0 = &acc2[hf * 32 + (2*j2+0) * 4];
                float* c1 = &acc2[hf * 32 + (2*j2+1) * 4];
                mma16816(c0, ah, bh[0], bh[1]); mma16816(c1, ah, bh[2], bh[3]);
                mma16816(c0, al, bh[0], bh[1]); mma16816(c1, al, bh[2], bh[3]);
                mma16816(c0, ah, bl[0], bl[1]); mma16816(c1, ah, bl[2], bl[3]);
            }
        }
    }

    // ---- epilogue 2 ----
    {
        const int r0 = wr + (lane >> 2), r1 = r0 + 8;
        const int ec = 2 * (lane & 3);
        const int d0 = sDst[r0], d1 = sDst[r1];
        float* eo0 = ef_out + (size_t)(e0 + r0) * 64;
        float* eo1 = ef_out + (size_t)(e0 + r1) * 64;
        float* ag0 = g_agg + (size_t)d0 * 64;
        float* ag1 = g_agg + (size_t)d1 * 64;
        #pragma unroll
        for (int j8 = 0; j8 < 8; j8++) {
            int cb = j8 * 8 + ec;
            float be0 = sB2b[cb], be1v = sB2b[cb + 1];
            float ba0 = sB2b[64 + cb], ba1v = sB2b[64 + cb + 1];
            float ex0 = acc2[j8*4+0] + be0, ex1 = acc2[j8*4+1] + be1v;
            float ax0 = acc2[32 + j8*4+0] + ba0, ax1 = acc2[32 + j8*4+1] + ba1v;
            float m0 = ex0 / (1.f + __expf(-ax0));
            float m1 = ex1 / (1.f + __expf(-ax1));
            *(float2*)(eo0 + cb) = make_float2(m0, m1);
            red2(ag0 + cb, m0, m1);
            float ey0 = acc2[j8*4+2] + be0, ey1 = acc2[j8*4+3] + be1v;
            float ay0 = acc2[32 + j8*4+2] + ba0, ay1 = acc2[32 + j8*4+3] + ba1v;
            float n0 = ey0 / (1.f + __expf(-ay0));
            float n1 = ey1 / (1.f + __expf(-ay1));
            *(float2*)(eo1 + cb) = make_float2(n0, n1);
            red2(ag1 + cb, n0, n1);
        }
    }
}

// ---------------------------------------------------------------------------
// Node kernel (HMMA, f32-acc 3-term)
// ---------------------------------------------------------------------------
#define NOFF_B1  69632
#define NOFF_W2  139264
#define NOFF_MSC 174080
#define NODE_SMEM 174848

__global__ __launch_bounds__(256, 1) void node_kernel(
    const float* __restrict__ nf,
    const float* __restrict__ bn1, const float* __restrict__ bn2,
    float* __restrict__ nf_out)
{
    extern __shared__ char smc[];
    const uint32_t smb = smem_u32(smc);
    const int tid = threadIdx.x, wid = tid >> 5, lane = tid & 31;
    const int m0 = blockIdx.x * 128;
    float* sB1b = (float*)(smc + NOFF_MSC);
    float* sB2b = (float*)(smc + NOFF_MSC + 512);

    #pragma unroll
    for (int i = 0; i < 17; i++)
        cpa16(smb + NOFF_B1 + (tid + 256 * i) * 16, (const char*)g_Wn1 + (tid + 256 * i) * 16);
    #pragma unroll
    for (int i = 0; i < 9; i++) {
        int idx = tid + 256 * i;
        if (idx < 2176) cpa16(smb + NOFF_W2 + idx * 16, (const char*)g_Wn2 + idx * 16);
    }
    CP_COMMIT();

    if (tid < 32) ((float4*)sB1b)[tid] = ((const float4*)bn1)[tid];
    else if (tid < 48) ((float4*)sB2b)[tid - 32] = ((const float4*)bn2)[tid - 32];

    {
        const int m = tid >> 1, h = tid & 1;
        const int node = m0 + m;
        const float4* src = (h == 0) ? (const float4*)(g_agg + (size_t)node * 64)
                                     : (const float4*)(nf + (size_t)node * 64);
        #pragma unroll
        for (int it = 0; it < 16; it++) {
            float4 v = (node < NN) ? src[it] : make_float4(0.f, 0.f, 0.f, 0.f);
            int k = h * 64 + it * 4;
            uint32_t h0 = packh2(v.x, v.y), h1 = packh2(v.z, v.w);
            float2 f0 = unpackh2(h0), f1 = unpackh2(h1);
            uint32_t l0 = packh2(v.x - f0.x, v.y - f0.y), l1 = packh2(v.z - f1.x, v.w - f1.y);
            *(uint2*)(smc + 0     + m * 272 + k * 2) = make_uint2(h0, h1);
            *(uint2*)(smc + 34816 + m * 272 + k * 2) = make_uint2(l0, l1);
        }
    }
    CP_WAIT0();
    __syncthreads();

    const int wr = wid * 16;
    const uint32_t aH = smb + (uint32_t)((wr + (lane & 15)) * 272 + ((lane >> 4) * 8) * 2);
    const uint32_t aL = aH + 34816;
    const uint32_t bln = (uint32_t)((((lane >> 4) << 3) + (lane & 7)) * 272 + (((lane >> 3) & 1) ? 16 : 0));

    float acc[64];
    #pragma unroll
    for (int i = 0; i < 64; i++) acc[i] = 0.f;
    {
        const uint32_t bH = smb + NOFF_B1 + bln;
        const uint32_t bL = bH + 34816;
        #pragma unroll
        for (int ks = 0; ks < 8; ks++) {
            uint32_t ah[4], al[4];
            ldsm4(ah, aH + ks * 32);
            ldsm4(al, aL + ks * 32);
            #pragma unroll
            for (int j2 = 0; j2 < 8; j2++) {
                uint32_t bh[4], bl[4];
                ldsm4(bh, bH + j2 * 4352 + ks * 32);
                ldsm4(bl, bL + j2 * 4352 + ks * 32);
                float* c0 = &acc[(2*j2+0)*4];
                float* c1 = &acc[(2*j2+1)*4];
                mma16816(c0, ah, bh[0], bh[1]); mma16816(c1, ah, bh[2], bh[3]);
                mma16816(c0, al, bh[0], bh[1]); mma16816(c1, al, bh[2], bh[3]);
                mma16816(c0, ah, bl[0], bl[1]); mma16816(c1, ah, bl[2], bl[3]);
            }
        }
    }

    uint32_t hH[32], hL[32];
    {
        const int ec = 2 * (lane & 3);
        #pragma unroll
        for (int j8 = 0; j8 < 16; j8++) {
            int cb = 8 * j8 + ec;
            float b0 = sB1b[cb], b1 = sB1b[cb + 1];
            float v0 = fmaxf(acc[4*j8+0] + b0, 0.f);
            float v1 = fmaxf(acc[4*j8+1] + b1, 0.f);
            float v2 = fmaxf(acc[4*j8+2] + b0, 0.f);
            float v3 = fmaxf(acc[4*j8+3] + b1, 0.f);
            uint32_t h01 = packh2(v0, v1);
            float2 f01 = unpackh2(h01);
            uint32_t l01 = packh2(v0 - f01.x, v1 - f01.y);
            uint32_t h23 = packh2(v2, v3);
            float2 f23 = unpackh2(h23);
            uint32_t l23 = packh2(v2 - f23.x, v3 - f23.y);
            hH[2*j8] = h01; hL[2*j8] = l01;
            hH[2*j8+1] = h23; hL[2*j8+1] = l23;
        }
    }

    float acc2[32];
    #pragma unroll
    for (int i = 0; i < 32; i++) acc2[i] = 0.f;
    {
        const uint32_t wb = smb + NOFF_W2 + bln;
        #pragma unroll
        for (int kc = 0; kc < 8; kc++) {
            uint32_t ah[4] = { hH[4*kc], hH[4*kc+1], hH[4*kc+2], hH[4*kc+3] };
            uint32_t al[4] = { hL[4*kc], hL[4*kc+1], hL[4*kc+2], hL[4*kc+3] };
            #pragma unroll
            for (int j2 = 0; j2 < 4; j2++) {
                uint32_t bh[4], bl[4];
                ldsm4(bh, wb + j2 * 4352 + kc * 32);
                ldsm4(bl, wb + 17408 + j2 * 4352 + kc * 32);
                float* c0 = &acc2[(2*j2+0)*4];
                float* c1 = &acc2[(2*j2+1)*4];
                mma16816(c0, ah, bh[0], bh[1]); mma16816(c1, ah, bh[2], bh[3]);
                mma16816(c0, al, bh[0], bh[1]); mma16816(c1, al, bh[2], bh[3]);
                mma16816(c0, ah, bl[0], bl[1]); mma16816(c1, ah, bl[2], bl[3]);
            }
        }
    }

    {
        const int r0 = wr + (lane >> 2);
        const int ec = 2 * (lane & 3);
        const int n0 = m0 + r0, n1 = n0 + 8;
        #pragma unroll
        for (int j8 = 0; j8 < 8; j8++) {
            int cb = 8 * j8 + ec;
            float b0 = sB2b[cb], b1 = sB2b[cb + 1];
            if (n0 < NN)
                *(float2*)(nf_out + (size_t)n0 * 64 + cb) =
                    make_float2(acc2[4*j8+0] + b0, acc2[4*j8+1] + b1);
            if (n1 < NN)
                *(float2*)(nf_out + (size_t)n1 * 64 + cb) =
                    make_float2(acc2[4*j8+2] + b0, acc2[4*j8+3] + b1);
        }
    }
}

// ---------------------------------------------------------------------------
extern "C" void kernel_launch(void* const* d_in, const int* in_sizes, int n_in,
                              void* d_out, int out_size)
{
    const float* nf  = (const float*)d_in[0];
    const float* ef  = (const float*)d_in[1];
    const float* We1 = (const float*)d_in[4];
    const float* be1 = (const float*)d_in[5];
    const float* We2 = (const float*)d_in[6];
    const float* be2 = (const float*)d_in[7];
    const float* Wa1 = (const float*)d_in[8];
    const float* ba1 = (const float*)d_in[9];
    const float* Wa2 = (const float*)d_in[10];
    const float* ba2 = (const float*)d_in[11];
    const float* Wn1 = (const float*)d_in[12];
    const float* bn1 = (const float*)d_in[13];
    const float* Wn2 = (const float*)d_in[14];
    const float* bn2 = (const float*)d_in[15];

    float* nf_out = (float*)d_out;
    float* ef_out = nf_out + (size_t)NN * 64;

    cudaFuncSetAttribute(prep_P_kernel, cudaFuncAttributeMaxDynamicSharedMemorySize, PREP_SMEM);
    cudaFuncSetAttribute(edge_kernel, cudaFuncAttributeMaxDynamicSharedMemorySize, EDGE_SMEM);
    cudaFuncSetAttribute(node_kernel, cudaFuncAttributeMaxDynamicSharedMemorySize, NODE_SMEM);

    prep_all<<<3830, 256>>>((const unsigned int*)d_in[2], We1, Wa1, We2, Wa2, Wn1, Wn2);
    prep_P_kernel<<<391, 256, PREP_SMEM>>>(nf);
    edge_kernel<<<E_EDGES / 64, 128, EDGE_SMEM>>>(
        ef, (const int*)d_in[2], (const int*)d_in[3],
        be1, ba1, be2, ba2, ef_out);
    node_kernel<<<391, 256, NODE_SMEM>>>(nf, bn1, bn2, nf_out);
}

// round 11
// speedup vs baseline: 1.0930x; 1.0930x over previous
#include <cuda_runtime.h>
#include <cuda_fp16.h>
#include <math.h>
#include <stdint.h>

#define E_EDGES 800000
#define NN      50000
typedef unsigned long long ull;

__device__ int    g_idx64;
__device__ float  g_agg[(size_t)NN * 64];
__device__ float  g_P[(size_t)50048 * 512];   // [node][ P_src(256) | P_dst(256) ]
__device__ __half g_B1e[2 * 256 * 72];        // ef-part W1: [hi|lo][256 n][72 kpad]
__device__ __half g_BP[2 * 512 * 72];         // P-prep W1:  [hi|lo][512 n][72 kpad]
__device__ __half g_W2[2 * 2 * 64 * 136];     // [gate][hi|lo][64 n][136 kpad]
__device__ __half g_Wn1[2 * 128 * 136];       // node W1: [hi|lo][128 n][136 kpad]
__device__ __half g_Wn2[2 * 64 * 136];        // node W2: [hi|lo][64 n][136 kpad]

// ---------------- helpers ----------------------------------------------------
__device__ __forceinline__ uint32_t smem_u32(const void* p) {
    uint32_t a;
    asm("{ .reg .u64 t; cvta.to.shared.u64 t, %1; cvt.u32.u64 %0, t; }" : "=r"(a) : "l"(p));
    return a;
}
__device__ __forceinline__ void ldsm4(uint32_t* r, uint32_t addr) {
    asm volatile("ldmatrix.sync.aligned.m8n8.x4.shared.b16 {%0,%1,%2,%3}, [%4];"
                 : "=r"(r[0]), "=r"(r[1]), "=r"(r[2]), "=r"(r[3]) : "r"(addr));
}
__device__ __forceinline__ void mma16816(float* c, const uint32_t* a, uint32_t b0, uint32_t b1) {
    asm volatile("mma.sync.aligned.m16n8k16.row.col.f32.f16.f16.f32 "
                 "{%0,%1,%2,%3}, {%4,%5,%6,%7}, {%8,%9}, {%0,%1,%2,%3};"
                 : "+f"(c[0]), "+f"(c[1]), "+f"(c[2]), "+f"(c[3])
                 : "r"(a[0]), "r"(a[1]), "r"(a[2]), "r"(a[3]), "r"(b0), "r"(b1));
}
__device__ __forceinline__ void cpa16(uint32_t dst, const void* src) {
    asm volatile("cp.async.cg.shared.global [%0], [%1], 16;" :: "r"(dst), "l"(src));
}
#define CP_COMMIT() asm volatile("cp.async.commit_group;" ::: "memory")
#define CP_WAIT0()  asm volatile("cp.async.wait_group 0;" ::: "memory")
#define CP_WAIT1()  asm volatile("cp.async.wait_group 1;" ::: "memory")
__device__ __forceinline__ void red2(float* p, float x, float y) {
    asm volatile("red.global.add.v2.f32 [%0], {%1,%2};" :: "l"(p), "f"(x), "f"(y) : "memory");
}
__device__ __forceinline__ uint32_t packh2(float x, float y) {
    __half2 h = __floats2half2_rn(x, y);
    return *(uint32_t*)&h;
}
__device__ __forceinline__ float2 unpackh2(uint32_t u) {
    return __half22float2(*(__half2*)&u);
}

// ---------------------------------------------------------------------------
// prep_all: fused zero+detect+all weight preps (one launch).
// blocks: [0,3125) zero agg | 3125 detect | [3126,3254) b1e | [3254,3382) w2
//         [3382,3638) bp | [3638,3766) wn1 | [3766,3830) wn2
// ---------------------------------------------------------------------------
__global__ void prep_all(const unsigned int* __restrict__ raw,
                         const float* __restrict__ We1, const float* __restrict__ Wa1,
                         const float* __restrict__ We2, const float* __restrict__ Wa2,
                         const float* __restrict__ Wn1, const float* __restrict__ Wn2)
{
    const int b = blockIdx.x, t = threadIdx.x;
    if (b < 3125) {
        ((float4*)g_agg)[b * 256 + t] = make_float4(0.f, 0.f, 0.f, 0.f);
    } else if (b == 3125) {
        __shared__ int any;
        if (t == 0) any = 0;
        __syncthreads();
        int f = 0;
        for (int i = t; i < 2048; i += blockDim.x)
            if (raw[2 * i + 1] != 0u) f = 1;
        if (f) atomicExch(&any, 1);
        __syncthreads();
        if (t == 0) g_idx64 = (any == 0) ? 1 : 0;
    } else if (b < 3254) {
        int gi = (b - 3126) * 256 + t;              // 32768
        int p = gi >> 14, r = gi & 16383;
        int n = r >> 6, kk = r & 63;
        int k = 128 + kk;
        float w = (n < 128) ? We1[k * 128 + n] : Wa1[k * 128 + (n - 128)];
        __half hi = __float2half_rn(w);
        __half v = (p == 0) ? hi : __float2half_rn(w - __half2float(hi));
        g_B1e[(p * 256 + n) * 72 + kk] = v;
    } else if (b < 3382) {
        int gi = (b - 3254) * 256 + t;              // 32768
        int g = gi >> 14, p = (gi >> 13) & 1;
        int r = gi & 8191, n = r >> 7, k = r & 127;
        const float* W = g ? Wa2 : We2;
        float w = W[k * 64 + n];
        __half hi = __float2half_rn(w);
        __half v = (p == 0) ? hi : __float2half_rn(w - __half2float(hi));
        g_W2[((g * 2 + p) * 64 + n) * 136 + k] = v;
    } else if (b < 3638) {
        int gi = (b - 3382) * 256 + t;              // 65536
        int p = gi >> 15, r = gi & 32767;
        int nIdx = r >> 6, kk = r & 63;
        int part = nIdx >> 8, c = nIdx & 255;
        int k = part * 64 + kk;
        float w = (c < 128) ? We1[k * 128 + c] : Wa1[k * 128 + (c - 128)];
        __half hi = __float2half_rn(w);
        __half v = (p == 0) ? hi : __float2half_rn(w - __half2float(hi));
        g_BP[(p * 512 + nIdx) * 72 + kk] = v;
    } else if (b < 3766) {
        int gi = (b - 3638) * 256 + t;              // 32768
        int p = gi >> 14, r = gi & 16383;
        int n = r >> 7, k = r & 127;
        float w = Wn1[k * 128 + n];
        __half hi = __float2half_rn(w);
        __half v = (p == 0) ? hi : __float2half_rn(w - __half2float(hi));
        g_Wn1[(p * 128 + n) * 136 + k] = v;
    } else {
        int gi = (b - 3766) * 256 + t;              // 16384
        int p = gi >> 13, r = gi & 8191;
        int n = r >> 7, k = r & 127;
        float w = Wn2[k * 64 + n];
        __half hi = __float2half_rn(w);
        __half v = (p == 0) ? hi : __float2half_rn(w - __half2float(hi));
        g_Wn2[(p * 64 + n) * 136 + k] = v;
    }
}

// ---------------------------------------------------------------------------
// prep_P: P[n][512] = nf[n] @ [W_src | W_dst], split-fp16 3-term HMMA.
// ---------------------------------------------------------------------------
#define PREP_SMEM 184320
__global__ __launch_bounds__(256, 1) void prep_P_kernel(const float* __restrict__ nf)
{
    extern __shared__ char smc[];
    const uint32_t smb = smem_u32(smc);
    const int tid = threadIdx.x, wid = tid >> 5, lane = tid & 31;
    const int m0 = blockIdx.x * 128;

    #pragma unroll
    for (int i = 0; i < 36; i++)
        cpa16(smb + 36864 + (tid + 256 * i) * 16, (const char*)g_BP + (tid + 256 * i) * 16);
    CP_COMMIT();

    {
        const int m = tid >> 1, h = tid & 1;
        const int node = m0 + m;
        const float* row = nf + (size_t)node * 64;
        #pragma unroll
        for (int it = 0; it < 8; it++) {
            int q = h * 8 + it;
            float4 v = (node < NN) ? ((const float4*)row)[q] : make_float4(0.f, 0.f, 0.f, 0.f);
            uint32_t h0 = packh2(v.x, v.y), h1 = packh2(v.z, v.w);
            float2 f0 = unpackh2(h0), f1 = unpackh2(h1);
            uint32_t l0 = packh2(v.x - f0.x, v.y - f0.y), l1 = packh2(v.z - f1.x, v.w - f1.y);
            *(uint2*)(smc + 0     + m * 144 + q * 8) = make_uint2(h0, h1);
            *(uint2*)(smc + 18432 + m * 144 + q * 8) = make_uint2(l0, l1);
        }
    }
    CP_WAIT0();
    __syncthreads();

    const int wr = wid * 16;
    const uint32_t aH = smb + (uint32_t)((wr + (lane & 15)) * 144 + ((lane >> 4) * 8) * 2);
    const uint32_t aL = aH + 18432;
    const uint32_t bln = (uint32_t)((((lane >> 4) << 3) + (lane & 7)) * 144 + (((lane >> 3) & 1) ? 16 : 0));
    const int r0 = wr + (lane >> 2);
    const int ec = 2 * (lane & 3);

    #pragma unroll
    for (int p = 0; p < 2; p++) {
        float acc[128];
        #pragma unroll
        for (int i = 0; i < 128; i++) acc[i] = 0.f;
        const uint32_t bH = smb + 36864  + (uint32_t)(p * 36864) + bln;
        const uint32_t bL = bH + 73728;
        #pragma unroll
        for (int ks = 0; ks < 4; ks++) {
            uint32_t ah[4], al[4];
            ldsm4(ah, aH + ks * 32);
            ldsm4(al, aL + ks * 32);
            #pragma unroll
            for (int j2 = 0; j2 < 16; j2++) {
                uint32_t bh[4], bl[4];
                ldsm4(bh, bH + j2 * 2304 + ks * 32);
                ldsm4(bl, bL + j2 * 2304 + ks * 32);
                mma16816(&acc[(2*j2+0)*4], ah, bh[0], bh[1]); mma16816(&acc[(2*j2+1)*4], ah, bh[2], bh[3]);
                mma16816(&acc[(2*j2+0)*4], al, bh[0], bh[1]); mma16816(&acc[(2*j2+1)*4], al, bh[2], bh[3]);
                mma16816(&acc[(2*j2+0)*4], ah, bl[0], bl[1]); mma16816(&acc[(2*j2+1)*4], ah, bl[2], bl[3]);
            }
        }
        #pragma unroll
        for (int j8 = 0; j8 < 32; j8++) {
            int cb = p * 256 + 8 * j8 + ec;
            *(float2*)(g_P + (size_t)(m0 + r0) * 512 + cb)     = make_float2(acc[4*j8+0], acc[4*j8+1]);
            *(float2*)(g_P + (size_t)(m0 + r0 + 8) * 512 + cb) = make_float2(acc[4*j8+2], acc[4*j8+3]);
        }
    }
}

// ---------------------------------------------------------------------------
// Edge kernel, occ-3, double-buffered B1 + R9 Psum-gather structure.
//  GEMM1:  A1H @0 (9216), A1L @9216 (9216), B1A @18432 (18432), B1B @36864 (18432)
//  gather: Psum @0 (64 x 260 f32 = 66560)            [A1/B1 dead after GEMM1]
//  GEMM2:  W2 @0 (69632: e-gate 34816 | a-gate 34816) [Psum dead after epi-1]
//  misc @69632 (2048) -> 71680 ; 3 CTAs x 71680 = 215040 <= 227KB
// ---------------------------------------------------------------------------
#define OFF_A1H  0
#define OFF_A1L  9216
#define OFF_B1A  18432
#define OFF_B1B  36864
#define OFF_MISC 69632
#define EDGE_SMEM 71680
#define PSTR 260

__global__ __launch_bounds__(128, 3) void edge_kernel(
    const float* __restrict__ ef,
    const int* __restrict__ rawsrc, const int* __restrict__ rawdst,
    const float* __restrict__ be1, const float* __restrict__ ba1,
    const float* __restrict__ be2, const float* __restrict__ ba2,
    float* __restrict__ ef_out)
{
    extern __shared__ char smc[];
    const uint32_t smb = smem_u32(smc);
    const int tid = threadIdx.x, wid = tid >> 5, lane = tid & 31;
    const int e0 = blockIdx.x * 64;

    int*   sSrc  = (int*)(smc + OFF_MISC);
    int*   sDst  = (int*)(smc + OFF_MISC + 256);
    float* sBias = (float*)(smc + OFF_MISC + 512);
    float* sB2b  = (float*)(smc + OFF_MISC + 1536);
    float* sPs   = (float*)(smc);

    // B1 stages 0,1 into the two buffers
    #pragma unroll
    for (int i = 0; i < 9; i++)
        cpa16(smb + OFF_B1A + (tid + 128 * i) * 16, (const char*)g_B1e + (tid + 128 * i) * 16);
    CP_COMMIT();
    #pragma unroll
    for (int i = 0; i < 9; i++)
        cpa16(smb + OFF_B1B + (tid + 128 * i) * 16, (const char*)g_B1e + 18432 + (tid + 128 * i) * 16);
    CP_COMMIT();

    const int is64 = g_idx64;
    if (tid < 64) sSrc[tid] = is64 ? rawsrc[2 * (e0 + tid)] : rawsrc[e0 + tid];
    else { int m = tid - 64; sDst[m] = is64 ? rawdst[2 * (e0 + m)] : rawdst[e0 + m]; }
    if (tid < 64)
        ((float4*)sBias)[tid] = (tid < 32) ? ((const float4*)be1)[tid] : ((const float4*)ba1)[tid - 32];
    else if (tid < 96)
        ((float4*)sB2b)[tid - 64] = (tid < 80) ? ((const float4*)be2)[tid - 64] : ((const float4*)ba2)[tid - 80];

    // gather ef rows, split hi/lo
    {
        const int m = tid >> 1, h = tid & 1;
        const float* row = ef + (size_t)(e0 + m) * 64;
        #pragma unroll
        for (int it = 0; it < 8; it++) {
            int q = h * 8 + it;
            float4 v = ((const float4*)row)[q];
            uint32_t h0 = packh2(v.x, v.y), h1 = packh2(v.z, v.w);
            float2 f0 = unpackh2(h0), f1 = unpackh2(h1);
            uint32_t l0 = packh2(v.x - f0.x, v.y - f0.y), l1 = packh2(v.z - f1.x, v.w - f1.y);
            *(uint2*)(smc + OFF_A1H + m * 144 + q * 8) = make_uint2(h0, h1);
            *(uint2*)(smc + OFF_A1L + m * 144 + q * 8) = make_uint2(l0, l1);
        }
    }

    const int wr = wid * 16;
    const uint32_t aH = smb + OFF_A1H + (uint32_t)((wr + (lane & 15)) * 144 + ((lane >> 4) * 8) * 2);
    const uint32_t aL = aH + 9216;
    const uint32_t bln = (uint32_t)((((lane >> 4) << 3) + (lane & 7)) * 144 + (((lane >> 3) & 1) ? 16 : 0));

    float acc[128];
    #pragma unroll
    for (int i = 0; i < 128; i++) acc[i] = 0.f;

    // ---- GEMM1, 4 stages {Wh n0, Wh n1, Wl n0, Wl n1}, double-buffered ----
    #pragma unroll
    for (int s = 0; s < 4; s++) {
        if (s < 3) { CP_WAIT1(); } else { CP_WAIT0(); }
        __syncthreads();
        const uint32_t bB = smb + ((s & 1) ? OFF_B1B : OFF_B1A) + bln;
        const int jbase = (s & 1) * 8;
        const bool p1 = (s < 2);
        #pragma unroll
        for (int ks = 0; ks < 4; ks++) {
            uint32_t ah[4], al[4];
            ldsm4(ah, aH + ks * 32);
            if (p1) ldsm4(al, aL + ks * 32);
            #pragma unroll
            for (int j2l = 0; j2l < 8; j2l++) {
                uint32_t bh[4];
                ldsm4(bh, bB + j2l * 2304 + ks * 32);
                int j2 = jbase + j2l;
                mma16816(&acc[(2*j2+0)*4], ah, bh[0], bh[1]);
                mma16816(&acc[(2*j2+1)*4], ah, bh[2], bh[3]);
                if (p1) {
                    mma16816(&acc[(2*j2+0)*4], al, bh[0], bh[1]);
                    mma16816(&acc[(2*j2+1)*4], al, bh[2], bh[3]);
                }
            }
        }
        __syncthreads();
        if (s < 2) {
            #pragma unroll
            for (int i = 0; i < 9; i++)
                cpa16(smb + ((s & 1) ? OFF_B1B : OFF_B1A) + (tid + 128 * i) * 16,
                      (const char*)g_B1e + (s + 2) * 18432 + (tid + 128 * i) * 16);
            CP_COMMIT();
        }
    }
    // A1/B1 dead. Gather Psum into [0, 66560).

    // ---- P gather: Psum[m][..] = P_src[src[m]] + P_dst[dst[m]][256:] ----
    {
        #pragma unroll
        for (int it = 0; it < 16; it++) {
            int m = (wid << 4) + it;
            const float4* ps = (const float4*)(g_P + (size_t)sSrc[m] * 512);
            const float4* pd = (const float4*)(g_P + (size_t)sDst[m] * 512 + 256);
            #pragma unroll
            for (int j = 0; j < 2; j++) {
                int f4 = lane + 32 * j;
                float4 a = ps[f4], b = pd[f4];
                *(float4*)(sPs + m * PSTR + f4 * 4) =
                    make_float4(a.x + b.x, a.y + b.y, a.z + b.z, a.w + b.w);
            }
        }
    }
    __syncthreads();

    // ---- epilogue 1: H = relu(acc + Psum + bias) -> hi/lo h2 regs ----
    uint32_t hH[64], hL[64];
    {
        const int r0 = wr + (lane >> 2);
        const int ec = 2 * (lane & 3);
        #pragma unroll
        for (int j8 = 0; j8 < 32; j8++) {
            int cb = 8 * j8 + ec;
            float2 p0 = *(float2*)(sPs + r0 * PSTR + cb);
            float2 p1v = *(float2*)(sPs + (r0 + 8) * PSTR + cb);
            float b0 = sBias[cb], b1 = sBias[cb + 1];
            float v0 = fmaxf(acc[4*j8+0] + p0.x + b0, 0.f);
            float v1 = fmaxf(acc[4*j8+1] + p0.y + b1, 0.f);
            float v2 = fmaxf(acc[4*j8+2] + p1v.x + b0, 0.f);
            float v3 = fmaxf(acc[4*j8+3] + p1v.y + b1, 0.f);
            uint32_t h01 = packh2(v0, v1);
            float2 f01 = unpackh2(h01);
            uint32_t l01 = packh2(v0 - f01.x, v1 - f01.y);
            uint32_t h23 = packh2(v2, v3);
            float2 f23 = unpackh2(h23);
            uint32_t l23 = packh2(v2 - f23.x, v3 - f23.y);
            hH[2*j8]   = h01; hL[2*j8]   = l01;
            hH[2*j8+1] = h23; hL[2*j8+1] = l23;
        }
    }
    __syncthreads();   // Psum reads done -> region reusable for W2

    // ---- stage W2: part1 (e gate) @0, part2 (a gate) @34816 ----
    #pragma unroll
    for (int i = 0; i < 17; i++)
        cpa16(smb + (tid + 128 * i) * 16, (const char*)g_W2 + (tid + 128 * i) * 16);
    CP_COMMIT();
    #pragma unroll
    for (int i = 0; i < 17; i++)
        cpa16(smb + 34816 + (tid + 128 * i) * 16, (const char*)g_W2 + 34816 + (tid + 128 * i) * 16);
    CP_COMMIT();
    CP_WAIT1();        // part1 ready
    __syncthreads();

    // ---- GEMM2: hf=0 (gate e), then wait part2, hf=1 (gate a) ----
    const uint32_t w2ln = (uint32_t)((((lane >> 4) << 3) + (lane & 7)) * 272 + (((lane >> 3) & 1) ? 16 : 0));
    float acc2[64];
    #pragma unroll
    for (int i = 0; i < 64; i++) acc2[i] = 0.f;

    #pragma unroll
    for (int hf = 0; hf < 2; hf++) {
        if (hf == 1) { CP_WAIT0(); __syncthreads(); }
        const uint32_t wb = smb + (uint32_t)(hf * 34816) + w2ln;
        #pragma unroll
        for (int kc = 0; kc < 8; kc++) {
            int jb = 2 * (hf * 16 + 2 * kc);
            uint32_t ah[4] = { hH[jb], hH[jb+1], hH[jb+2], hH[jb+3] };
            uint32_t al[4] = { hL[jb], hL[jb+1], hL[jb+2], hL[jb+3] };
            #pragma unroll
            for (int j2 = 0; j2 < 4; j2++) {
                uint32_t bh[4], bl[4];
                ldsm4(bh, wb + j2 * 4352 + kc * 32);
                ldsm4(bl, wb + 17408 + j2 * 4352 + kc * 32);
                float* c0 = &acc2[hf * 32 + (2*j2+0) * 4];
                float* c1 = &acc2[hf * 32 + (2*j2+1) * 4];
                mma16816(c0, ah, bh[0], bh[1]); mma16816(c1, ah, bh[2], bh[3]);
                mma16816(c0, al, bh[0], bh[1]); mma16816(c1, al, bh[2], bh[3]);
                mma16816(c0, ah, bl[0], bl[1]); mma16816(c1, ah, bl[2], bl[3]);
            }
        }
    }

    // ---- epilogue 2 ----
    {
        const int r0 = wr + (lane >> 2), r1 = r0 + 8;
        const int ec = 2 * (lane & 3);
        const int d0 = sDst[r0], d1 = sDst[r1];
        float* eo0 = ef_out + (size_t)(e0 + r0) * 64;
        float* eo1 = ef_out + (size_t)(e0 + r1) * 64;
        float* ag0 = g_agg + (size_t)d0 * 64;
        float* ag1 = g_agg + (size_t)d1 * 64;
        #pragma unroll
        for (int j8 = 0; j8 < 8; j8++) {
            int cb = j8 * 8 + ec;
            float be0 = sB2b[cb], be1v = sB2b[cb + 1];
            float ba0 = sB2b[64 + cb], ba1v = sB2b[64 + cb + 1];
            float ex0 = acc2[j8*4+0] + be0, ex1 = acc2[j8*4+1] + be1v;
            float ax0 = acc2[32 + j8*4+0] + ba0, ax1 = acc2[32 + j8*4+1] + ba1v;
            float m0 = ex0 / (1.f + __expf(-ax0));
            float m1 = ex1 / (1.f + __expf(-ax1));
            *(float2*)(eo0 + cb) = make_float2(m0, m1);
            red2(ag0 + cb, m0, m1);
            float ey0 = acc2[j8*4+2] + be0, ey1 = acc2[j8*4+3] + be1v;
            float ay0 = acc2[32 + j8*4+2] + ba0, ay1 = acc2[32 + j8*4+3] + ba1v;
            float n0 = ey0 / (1.f + __expf(-ay0));
            float n1 = ey1 / (1.f + __expf(-ay1));
            *(float2*)(eo1 + cb) = make_float2(n0, n1);
            red2(ag1 + cb, n0, n1);
        }
    }
}

// ---------------------------------------------------------------------------
// Node kernel (HMMA, f32-acc 3-term)
// ---------------------------------------------------------------------------
#define NOFF_B1  69632
#define NOFF_W2  139264
#define NOFF_MSC 174080
#define NODE_SMEM 174848

__global__ __launch_bounds__(256, 1) void node_kernel(
    const float* __restrict__ nf,
    const float* __restrict__ bn1, const float* __restrict__ bn2,
    float* __restrict__ nf_out)
{
    extern __shared__ char smc[];
    const uint32_t smb = smem_u32(smc);
    const int tid = threadIdx.x, wid = tid >> 5, lane = tid & 31;
    const int m0 = blockIdx.x * 128;
    float* sB1b = (float*)(smc + NOFF_MSC);
    float* sB2b = (float*)(smc + NOFF_MSC + 512);

    #pragma unroll
    for (int i = 0; i < 17; i++)
        cpa16(smb + NOFF_B1 + (tid + 256 * i) * 16, (const char*)g_Wn1 + (tid + 256 * i) * 16);
    #pragma unroll
    for (int i = 0; i < 9; i++) {
        int idx = tid + 256 * i;
        if (idx < 2176) cpa16(smb + NOFF_W2 + idx * 16, (const char*)g_Wn2 + idx * 16);
    }
    CP_COMMIT();

    if (tid < 32) ((float4*)sB1b)[tid] = ((const float4*)bn1)[tid];
    else if (tid < 48) ((float4*)sB2b)[tid - 32] = ((const float4*)bn2)[tid - 32];

    {
        const int m = tid >> 1, h = tid & 1;
        const int node = m0 + m;
        const float4* src = (h == 0) ? (const float4*)(g_agg + (size_t)node * 64)
                                     : (const float4*)(nf + (size_t)node * 64);
        #pragma unroll
        for (int it = 0; it < 16; it++) {
            float4 v = (node < NN) ? src[it] : make_float4(0.f, 0.f, 0.f, 0.f);
            int k = h * 64 + it * 4;
            uint32_t h0 = packh2(v.x, v.y), h1 = packh2(v.z, v.w);
            float2 f0 = unpackh2(h0), f1 = unpackh2(h1);
            uint32_t l0 = packh2(v.x - f0.x, v.y - f0.y), l1 = packh2(v.z - f1.x, v.w - f1.y);
            *(uint2*)(smc + 0     + m * 272 + k * 2) = make_uint2(h0, h1);
            *(uint2*)(smc + 34816 + m * 272 + k * 2) = make_uint2(l0, l1);
        }
    }
    CP_WAIT0();
    __syncthreads();

    const int wr = wid * 16;
    const uint32_t aH = smb + (uint32_t)((wr + (lane & 15)) * 272 + ((lane >> 4) * 8) * 2);
    const uint32_t aL = aH + 34816;
    const uint32_t bln = (uint32_t)((((lane >> 4) << 3) + (lane & 7)) * 272 + (((lane >> 3) & 1) ? 16 : 0));

    float acc[64];
    #pragma unroll
    for (int i = 0; i < 64; i++) acc[i] = 0.f;
    {
        const uint32_t bH = smb + NOFF_B1 + bln;
        const uint32_t bL = bH + 34816;
        #pragma unroll
        for (int ks = 0; ks < 8; ks++) {
            uint32_t ah[4], al[4];
            ldsm4(ah, aH + ks * 32);
            ldsm4(al, aL + ks * 32);
            #pragma unroll
            for (int j2 = 0; j2 < 8; j2++) {
                uint32_t bh[4], bl[4];
                ldsm4(bh, bH + j2 * 4352 + ks * 32);
                ldsm4(bl, bL + j2 * 4352 + ks * 32);
                float* c0 = &acc[(2*j2+0)*4];
                float* c1 = &acc[(2*j2+1)*4];
                mma16816(c0, ah, bh[0], bh[1]); mma16816(c1, ah, bh[2], bh[3]);
                mma16816(c0, al, bh[0], bh[1]); mma16816(c1, al, bh[2], bh[3]);
                mma16816(c0, ah, bl[0], bl[1]); mma16816(c1, ah, bl[2], bl[3]);
            }
        }
    }

    uint32_t hH[32], hL[32];
    {
        const int ec = 2 * (lane & 3);
        #pragma unroll
        for (int j8 = 0; j8 < 16; j8++) {
            int cb = 8 * j8 + ec;
            float b0 = sB1b[cb], b1 = sB1b[cb + 1];
            float v0 = fmaxf(acc[4*j8+0] + b0, 0.f);
            float v1 = fmaxf(acc[4*j8+1] + b1, 0.f);
            float v2 = fmaxf(acc[4*j8+2] + b0, 0.f);
            float v3 = fmaxf(acc[4*j8+3] + b1, 0.f);
            uint32_t h01 = packh2(v0, v1);
            float2 f01 = unpackh2(h01);
            uint32_t l01 = packh2(v0 - f01.x, v1 - f01.y);
            uint32_t h23 = packh2(v2, v3);
            float2 f23 = unpackh2(h23);
            uint32_t l23 = packh2(v2 - f23.x, v3 - f23.y);
            hH[2*j8] = h01; hL[2*j8] = l01;
            hH[2*j8+1] = h23; hL[2*j8+1] = l23;
        }
    }

    float acc2[32];
    #pragma unroll
    for (int i = 0; i < 32; i++) acc2[i] = 0.f;
    {
        const uint32_t wb = smb + NOFF_W2 + bln;
        #pragma unroll
        for (int kc = 0; kc < 8; kc++) {
            uint32_t ah[4] = { hH[4*kc], hH[4*kc+1], hH[4*kc+2], hH[4*kc+3] };
            uint32_t al[4] = { hL[4*kc], hL[4*kc+1], hL[4*kc+2], hL[4*kc+3] };
            #pragma unroll
            for (int j2 = 0; j2 < 4; j2++) {
                uint32_t bh[4], bl[4];
                ldsm4(bh, wb + j2 * 4352 + kc * 32);
                ldsm4(bl, wb + 17408 + j2 * 4352 + kc * 32);
                float* c0 = &acc2[(2*j2+0)*4];
                float* c1 = &acc2[(2*j2+1)*4];
                mma16816(c0, ah, bh[0], bh[1]); mma16816(c1, ah, bh[2], bh[3]);
                mma16816(c0, al, bh[0], bh[1]); mma16816(c1, al, bh[2], bh[3]);
                mma16816(c0, ah, bl[0], bl[1]); mma16816(c1, ah, bl[2], bl[3]);
            }
        }
    }

    {
        const int r0 = wr + (lane >> 2);
        const int ec = 2 * (lane & 3);
        const int n0 = m0 + r0, n1 = n0 + 8;
        #pragma unroll
        for (int j8 = 0; j8 < 8; j8++) {
            int cb = 8 * j8 + ec;
            float b0 = sB2b[cb], b1 = sB2b[cb + 1];
            if (n0 < NN)
                *(float2*)(nf_out + (size_t)n0 * 64 + cb) =
                    make_float2(acc2[4*j8+0] + b0, acc2[4*j8+1] + b1);
            if (n1 < NN)
                *(float2*)(nf_out + (size_t)n1 * 64 + cb) =
                    make_float2(acc2[4*j8+2] + b0, acc2[4*j8+3] + b1);
        }
    }
}

// ---------------------------------------------------------------------------
extern "C" void kernel_launch(void* const* d_in, const int* in_sizes, int n_in,
                              void* d_out, int out_size)
{
    const float* nf  = (const float*)d_in[0];
    const float* ef  = (const float*)d_in[1];
    const float* We1 = (const float*)d_in[4];
    const float* be1 = (const float*)d_in[5];
    const float* We2 = (const float*)d_in[6];
    const float* be2 = (const float*)d_in[7];
    const float* Wa1 = (const float*)d_in[8];
    const float* ba1 = (const float*)d_in[9];
    const float* Wa2 = (const float*)d_in[10];
    const float* ba2 = (const float*)d_in[11];
    const float* Wn1 = (const float*)d_in[12];
    const float* bn1 = (const float*)d_in[13];
    const float* Wn2 = (const float*)d_in[14];
    const float* bn2 = (const float*)d_in[15];

    float* nf_out = (float*)d_out;
    float* ef_out = nf_out + (size_t)NN * 64;

    cudaFuncSetAttribute(prep_P_kernel, cudaFuncAttributeMaxDynamicSharedMemorySize, PREP_SMEM);
    cudaFuncSetAttribute(edge_kernel, cudaFuncAttributeMaxDynamicSharedMemorySize, EDGE_SMEM);
    cudaFuncSetAttribute(node_kernel, cudaFuncAttributeMaxDynamicSharedMemorySize, NODE_SMEM);

    prep_all<<<3830, 256>>>((const unsigned int*)d_in[2], We1, Wa1, We2, Wa2, Wn1, Wn2);
    prep_P_kernel<<<391, 256, PREP_SMEM>>>(nf);
    edge_kernel<<<E_EDGES / 64, 128, EDGE_SMEM>>>(
        ef, (const int*)d_in[2], (const int*)d_in[3],
        be1, ba1, be2, ba2, ef_out);
    node_kernel<<<391, 256, NODE_SMEM>>>(nf, bn1, bn2, nf_out);
}

// round 12
// speedup vs baseline: 1.1805x; 1.0800x over previous
#include <cuda_runtime.h>
#include <cuda_fp16.h>
#include <math.h>
#include <stdint.h>

#define E_EDGES 800000
#define NN      50000
typedef unsigned long long ull;

__device__ int    g_idx64;
__device__ float  g_agg[(size_t)NN * 64];
__device__ float  g_P[(size_t)50048 * 512];   // [node][ P_src(256) | P_dst(256) ]
__device__ __half g_B1e[2 * 256 * 72];        // ef-part W1: [hi|lo][256 n][72 kpad] (lo unused now)
__device__ __half g_BP[2 * 512 * 72];         // P-prep W1:  [hi|lo][512 n][72 kpad]
__device__ __half g_W2[2 * 2 * 64 * 136];     // [gate][hi|lo][64 n][136 kpad]
__device__ __half g_Wn1[2 * 128 * 136];       // node W1: [hi|lo][128 n][136 kpad]
__device__ __half g_Wn2[2 * 64 * 136];        // node W2: [hi|lo][64 n][136 kpad]

// ---------------- helpers ----------------------------------------------------
__device__ __forceinline__ uint32_t smem_u32(const void* p) {
    uint32_t a;
    asm("{ .reg .u64 t; cvta.to.shared.u64 t, %1; cvt.u32.u64 %0, t; }" : "=r"(a) : "l"(p));
    return a;
}
__device__ __forceinline__ void ldsm4(uint32_t* r, uint32_t addr) {
    asm volatile("ldmatrix.sync.aligned.m8n8.x4.shared.b16 {%0,%1,%2,%3}, [%4];"
                 : "=r"(r[0]), "=r"(r[1]), "=r"(r[2]), "=r"(r[3]) : "r"(addr));
}
__device__ __forceinline__ void mma16816(float* c, const uint32_t* a, uint32_t b0, uint32_t b1) {
    asm volatile("mma.sync.aligned.m16n8k16.row.col.f32.f16.f16.f32 "
                 "{%0,%1,%2,%3}, {%4,%5,%6,%7}, {%8,%9}, {%0,%1,%2,%3};"
                 : "+f"(c[0]), "+f"(c[1]), "+f"(c[2]), "+f"(c[3])
                 : "r"(a[0]), "r"(a[1]), "r"(a[2]), "r"(a[3]), "r"(b0), "r"(b1));
}
__device__ __forceinline__ void cpa16(uint32_t dst, const void* src) {
    asm volatile("cp.async.cg.shared.global [%0], [%1], 16;" :: "r"(dst), "l"(src));
}
#define CP_COMMIT() asm volatile("cp.async.commit_group;" ::: "memory")
#define CP_WAIT0()  asm volatile("cp.async.wait_group 0;" ::: "memory")
#define CP_WAIT1()  asm volatile("cp.async.wait_group 1;" ::: "memory")
__device__ __forceinline__ void red2(float* p, float x, float y) {
    asm volatile("red.global.add.v2.f32 [%0], {%1,%2};" :: "l"(p), "f"(x), "f"(y) : "memory");
}
__device__ __forceinline__ uint32_t packh2(float x, float y) {
    __half2 h = __floats2half2_rn(x, y);
    return *(uint32_t*)&h;
}
__device__ __forceinline__ float2 unpackh2(uint32_t u) {
    return __half22float2(*(__half2*)&u);
}

// ---------------------------------------------------------------------------
// prep_all: fused zero+detect+all weight preps (one launch).
// ---------------------------------------------------------------------------
__global__ void prep_all(const unsigned int* __restrict__ raw,
                         const float* __restrict__ We1, const float* __restrict__ Wa1,
                         const float* __restrict__ We2, const float* __restrict__ Wa2,
                         const float* __restrict__ Wn1, const float* __restrict__ Wn2)
{
    const int b = blockIdx.x, t = threadIdx.x;
    if (b < 3125) {
        ((float4*)g_agg)[b * 256 + t] = make_float4(0.f, 0.f, 0.f, 0.f);
    } else if (b == 3125) {
        __shared__ int any;
        if (t == 0) any = 0;
        __syncthreads();
        int f = 0;
        for (int i = t; i < 2048; i += blockDim.x)
            if (raw[2 * i + 1] != 0u) f = 1;
        if (f) atomicExch(&any, 1);
        __syncthreads();
        if (t == 0) g_idx64 = (any == 0) ? 1 : 0;
    } else if (b < 3254) {
        int gi = (b - 3126) * 256 + t;              // 32768
        int p = gi >> 14, r = gi & 16383;
        int n = r >> 6, kk = r & 63;
        int k = 128 + kk;
        float w = (n < 128) ? We1[k * 128 + n] : Wa1[k * 128 + (n - 128)];
        __half hi = __float2half_rn(w);
        __half v = (p == 0) ? hi : __float2half_rn(w - __half2float(hi));
        g_B1e[(p * 256 + n) * 72 + kk] = v;
    } else if (b < 3382) {
        int gi = (b - 3254) * 256 + t;              // 32768
        int g = gi >> 14, p = (gi >> 13) & 1;
        int r = gi & 8191, n = r >> 7, k = r & 127;
        const float* W = g ? Wa2 : We2;
        float w = W[k * 64 + n];
        __half hi = __float2half_rn(w);
        __half v = (p == 0) ? hi : __float2half_rn(w - __half2float(hi));
        g_W2[((g * 2 + p) * 64 + n) * 136 + k] = v;
    } else if (b < 3638) {
        int gi = (b - 3382) * 256 + t;              // 65536
        int p = gi >> 15, r = gi & 32767;
        int nIdx = r >> 6, kk = r & 63;
        int part = nIdx >> 8, c = nIdx & 255;
        int k = part * 64 + kk;
        float w = (c < 128) ? We1[k * 128 + c] : Wa1[k * 128 + (c - 128)];
        __half hi = __float2half_rn(w);
        __half v = (p == 0) ? hi : __float2half_rn(w - __half2float(hi));
        g_BP[(p * 512 + nIdx) * 72 + kk] = v;
    } else if (b < 3766) {
        int gi = (b - 3638) * 256 + t;              // 32768
        int p = gi >> 14, r = gi & 16383;
        int n = r >> 7, k = r & 127;
        float w = Wn1[k * 128 + n];
        __half hi = __float2half_rn(w);
        __half v = (p == 0) ? hi : __float2half_rn(w - __half2float(hi));
        g_Wn1[(p * 128 + n) * 136 + k] = v;
    } else {
        int gi = (b - 3766) * 256 + t;              // 16384
        int p = gi >> 13, r = gi & 8191;
        int n = r >> 7, k = r & 127;
        float w = Wn2[k * 64 + n];
        __half hi = __float2half_rn(w);
        __half v = (p == 0) ? hi : __float2half_rn(w - __half2float(hi));
        g_Wn2[(p * 64 + n) * 136 + k] = v;
    }
}

// ---------------------------------------------------------------------------
// prep_P: P[n][512] = nf[n] @ [W_src | W_dst], split-fp16 3-term HMMA.
// ---------------------------------------------------------------------------
#define PREP_SMEM 184320
__global__ __launch_bounds__(256, 1) void prep_P_kernel(const float* __restrict__ nf)
{
    extern __shared__ char smc[];
    const uint32_t smb = smem_u32(smc);
    const int tid = threadIdx.x, wid = tid >> 5, lane = tid & 31;
    const int m0 = blockIdx.x * 128;

    #pragma unroll
    for (int i = 0; i < 36; i++)
        cpa16(smb + 36864 + (tid + 256 * i) * 16, (const char*)g_BP + (tid + 256 * i) * 16);
    CP_COMMIT();

    {
        const int m = tid >> 1, h = tid & 1;
        const int node = m0 + m;
        const float* row = nf + (size_t)node * 64;
        #pragma unroll
        for (int it = 0; it < 8; it++) {
            int q = h * 8 + it;
            float4 v = (node < NN) ? ((const float4*)row)[q] : make_float4(0.f, 0.f, 0.f, 0.f);
            uint32_t h0 = packh2(v.x, v.y), h1 = packh2(v.z, v.w);
            float2 f0 = unpackh2(h0), f1 = unpackh2(h1);
            uint32_t l0 = packh2(v.x - f0.x, v.y - f0.y), l1 = packh2(v.z - f1.x, v.w - f1.y);
            *(uint2*)(smc + 0     + m * 144 + q * 8) = make_uint2(h0, h1);
            *(uint2*)(smc + 18432 + m * 144 + q * 8) = make_uint2(l0, l1);
        }
    }
    CP_WAIT0();
    __syncthreads();

    const int wr = wid * 16;
    const uint32_t aH = smb + (uint32_t)((wr + (lane & 15)) * 144 + ((lane >> 4) * 8) * 2);
    const uint32_t aL = aH + 18432;
    const uint32_t bln = (uint32_t)((((lane >> 4) << 3) + (lane & 7)) * 144 + (((lane >> 3) & 1) ? 16 : 0));
    const int r0 = wr + (lane >> 2);
    const int ec = 2 * (lane & 3);

    #pragma unroll
    for (int p = 0; p < 2; p++) {
        float acc[128];
        #pragma unroll
        for (int i = 0; i < 128; i++) acc[i] = 0.f;
        const uint32_t bH = smb + 36864  + (uint32_t)(p * 36864) + bln;
        const uint32_t bL = bH + 73728;
        #pragma unroll
        for (int ks = 0; ks < 4; ks++) {
            uint32_t ah[4], al[4];
            ldsm4(ah, aH + ks * 32);
            ldsm4(al, aL + ks * 32);
            #pragma unroll
            for (int j2 = 0; j2 < 16; j2++) {
                uint32_t bh[4], bl[4];
                ldsm4(bh, bH + j2 * 2304 + ks * 32);
                ldsm4(bl, bL + j2 * 2304 + ks * 32);
                mma16816(&acc[(2*j2+0)*4], ah, bh[0], bh[1]); mma16816(&acc[(2*j2+1)*4], ah, bh[2], bh[3]);
                mma16816(&acc[(2*j2+0)*4], al, bh[0], bh[1]); mma16816(&acc[(2*j2+1)*4], al, bh[2], bh[3]);
                mma16816(&acc[(2*j2+0)*4], ah, bl[0], bl[1]); mma16816(&acc[(2*j2+1)*4], ah, bl[2], bl[3]);
            }
        }
        #pragma unroll
        for (int j8 = 0; j8 < 32; j8++) {
            int cb = p * 256 + 8 * j8 + ec;
            *(float2*)(g_P + (size_t)(m0 + r0) * 512 + cb)     = make_float2(acc[4*j8+0], acc[4*j8+1]);
            *(float2*)(g_P + (size_t)(m0 + r0 + 8) * 512 + cb) = make_float2(acc[4*j8+2], acc[4*j8+3]);
        }
    }
}

// ---------------------------------------------------------------------------
// Edge kernel, occ-3. GEMM1: ef-part in PLAIN fp16 (1 term, K=64), both B
// chunks preloaded — no mid-GEMM reloads. GEMM2 stays 3-term.
//  GEMM1:  A1H @0 (9216), B1A @18432 (18432), B1B @36864 (18432)
//  gather: Psum @0 (64 x 260 f32 = 66560)            [A1/B1 dead after GEMM1]
//  GEMM2:  W2 @0 (69632)                              [Psum dead after epi-1]
//  misc @69632 (2048) -> 71680 ; 3 CTAs x 71680 = 215040 <= 227KB
// ---------------------------------------------------------------------------
#define OFF_A1H  0
#define OFF_B1A  18432
#define OFF_B1B  36864
#define OFF_MISC 69632
#define EDGE_SMEM 71680
#define PSTR 260

__global__ __launch_bounds__(128, 3) void edge_kernel(
    const float* __restrict__ ef,
    const int* __restrict__ rawsrc, const int* __restrict__ rawdst,
    const float* __restrict__ be1, const float* __restrict__ ba1,
    const float* __restrict__ be2, const float* __restrict__ ba2,
    float* __restrict__ ef_out)
{
    extern __shared__ char smc[];
    const uint32_t smb = smem_u32(smc);
    const int tid = threadIdx.x, wid = tid >> 5, lane = tid & 31;
    const int e0 = blockIdx.x * 64;

    int*   sSrc  = (int*)(smc + OFF_MISC);
    int*   sDst  = (int*)(smc + OFF_MISC + 256);
    float* sBias = (float*)(smc + OFF_MISC + 512);
    float* sB2b  = (float*)(smc + OFF_MISC + 1536);
    float* sPs   = (float*)(smc);

    // B1 hi: both n-chunks preloaded
    #pragma unroll
    for (int i = 0; i < 9; i++)
        cpa16(smb + OFF_B1A + (tid + 128 * i) * 16, (const char*)g_B1e + (tid + 128 * i) * 16);
    CP_COMMIT();
    #pragma unroll
    for (int i = 0; i < 9; i++)
        cpa16(smb + OFF_B1B + (tid + 128 * i) * 16, (const char*)g_B1e + 18432 + (tid + 128 * i) * 16);
    CP_COMMIT();

    const int is64 = g_idx64;
    if (tid < 64) sSrc[tid] = is64 ? rawsrc[2 * (e0 + tid)] : rawsrc[e0 + tid];
    else { int m = tid - 64; sDst[m] = is64 ? rawdst[2 * (e0 + m)] : rawdst[e0 + m]; }
    if (tid < 64)
        ((float4*)sBias)[tid] = (tid < 32) ? ((const float4*)be1)[tid] : ((const float4*)ba1)[tid - 32];
    else if (tid < 96)
        ((float4*)sB2b)[tid - 64] = (tid < 80) ? ((const float4*)be2)[tid - 64] : ((const float4*)ba2)[tid - 80];

    // gather ef rows -> fp16 (hi only)
    {
        const int m = tid >> 1, h = tid & 1;
        const float* row = ef + (size_t)(e0 + m) * 64;
        #pragma unroll
        for (int it = 0; it < 8; it++) {
            int q = h * 8 + it;
            float4 v = ((const float4*)row)[q];
            uint32_t h0 = packh2(v.x, v.y), h1 = packh2(v.z, v.w);
            *(uint2*)(smc + OFF_A1H + m * 144 + q * 8) = make_uint2(h0, h1);
        }
    }

    const int wr = wid * 16;
    const uint32_t aH = smb + OFF_A1H + (uint32_t)((wr + (lane & 15)) * 144 + ((lane >> 4) * 8) * 2);
    const uint32_t bln = (uint32_t)((((lane >> 4) << 3) + (lane & 7)) * 144 + (((lane >> 3) & 1) ? 16 : 0));

    float acc[128];
    #pragma unroll
    for (int i = 0; i < 128; i++) acc[i] = 0.f;

    // ---- GEMM1: 2 stages {Wh n0-127, Wh n128-255}, plain fp16 ----
    #pragma unroll
    for (int s = 0; s < 2; s++) {
        if (s == 0) { CP_WAIT1(); } else { CP_WAIT0(); }
        __syncthreads();
        const uint32_t bB = smb + (s ? OFF_B1B : OFF_B1A) + bln;
        const int jbase = s * 8;
        #pragma unroll
        for (int ks = 0; ks < 4; ks++) {
            uint32_t ah[4];
            ldsm4(ah, aH + ks * 32);
            #pragma unroll
            for (int j2l = 0; j2l < 8; j2l++) {
                uint32_t bh[4];
                ldsm4(bh, bB + j2l * 2304 + ks * 32);
                int j2 = jbase + j2l;
                mma16816(&acc[(2*j2+0)*4], ah, bh[0], bh[1]);
                mma16816(&acc[(2*j2+1)*4], ah, bh[2], bh[3]);
            }
        }
    }
    __syncthreads();
    // A1/B1 dead. Gather Psum into [0, 66560).

    // ---- P gather: Psum[m][..] = P_src[src[m]] + P_dst[dst[m]][256:] ----
    {
        #pragma unroll
        for (int it = 0; it < 16; it++) {
            int m = (wid << 4) + it;
            const float4* ps = (const float4*)(g_P + (size_t)sSrc[m] * 512);
            const float4* pd = (const float4*)(g_P + (size_t)sDst[m] * 512 + 256);
            #pragma unroll
            for (int j = 0; j < 2; j++) {
                int f4 = lane + 32 * j;
                float4 a = ps[f4], b = pd[f4];
                *(float4*)(sPs + m * PSTR + f4 * 4) =
                    make_float4(a.x + b.x, a.y + b.y, a.z + b.z, a.w + b.w);
            }
        }
    }
    __syncthreads();

    // ---- epilogue 1: H = relu(acc + Psum + bias) -> hi/lo h2 regs ----
    uint32_t hH[64], hL[64];
    {
        const int r0 = wr + (lane >> 2);
        const int ec = 2 * (lane & 3);
        #pragma unroll
        for (int j8 = 0; j8 < 32; j8++) {
            int cb = 8 * j8 + ec;
            float2 p0 = *(float2*)(sPs + r0 * PSTR + cb);
            float2 p1v = *(float2*)(sPs + (r0 + 8) * PSTR + cb);
            float b0 = sBias[cb], b1 = sBias[cb + 1];
            float v0 = fmaxf(acc[4*j8+0] + p0.x + b0, 0.f);
            float v1 = fmaxf(acc[4*j8+1] + p0.y + b1, 0.f);
            float v2 = fmaxf(acc[4*j8+2] + p1v.x + b0, 0.f);
            float v3 = fmaxf(acc[4*j8+3] + p1v.y + b1, 0.f);
            uint32_t h01 = packh2(v0, v1);
            float2 f01 = unpackh2(h01);
            uint32_t l01 = packh2(v0 - f01.x, v1 - f01.y);
            uint32_t h23 = packh2(v2, v3);
            float2 f23 = unpackh2(h23);
            uint32_t l23 = packh2(v2 - f23.x, v3 - f23.y);
            hH[2*j8]   = h01; hL[2*j8]   = l01;
            hH[2*j8+1] = h23; hL[2*j8+1] = l23;
        }
    }
    __syncthreads();   // Psum reads done -> region reusable for W2

    // ---- stage W2: part1 (e gate) @0, part2 (a gate) @34816 ----
    #pragma unroll
    for (int i = 0; i < 17; i++)
        cpa16(smb + (tid + 128 * i) * 16, (const char*)g_W2 + (tid + 128 * i) * 16);
    CP_COMMIT();
    #pragma unroll
    for (int i = 0; i < 17; i++)
        cpa16(smb + 34816 + (tid + 128 * i) * 16, (const char*)g_W2 + 34816 + (tid + 128 * i) * 16);
    CP_COMMIT();
    CP_WAIT1();        // part1 ready
    __syncthreads();

    // ---- GEMM2: hf=0 (gate e), then wait part2, hf=1 (gate a) ----
    const uint32_t w2ln = (uint32_t)((((lane >> 4) << 3) + (lane & 7)) * 272 + (((lane >> 3) & 1) ? 16 : 0));
    float acc2[64];
    #pragma unroll
    for (int i = 0; i < 64; i++) acc2[i] = 0.f;

    #pragma unroll
    for (int hf = 0; hf < 2; hf++) {
        if (hf == 1) { CP_WAIT0(); __syncthreads(); }
        const uint32_t wb = smb + (uint32_t)(hf * 34816) + w2ln;
        #pragma unroll
        for (int kc = 0; kc < 8; kc++) {
            int jb = 2 * (hf * 16 + 2 * kc);
            uint32_t ah[4] = { hH[jb], hH[jb+1], hH[jb+2], hH[jb+3] };
            uint32_t al[4] = { hL[jb], hL[jb+1], hL[jb+2], hL[jb+3] };
            #pragma unroll
            for (int j2 = 0; j2 < 4; j2++) {
                uint32_t bh[4], bl[4];
                ldsm4(bh, wb + j2 * 4352 + kc * 32);
                ldsm4(bl, wb + 17408 + j2 * 4352 + kc * 32);
                float* c0 = &acc2[hf * 32 + (2*j2+0) * 4];
                float* c1 = &acc2[hf * 32 + (2*j2+1) * 4];
                mma16816(c0, ah, bh[0], bh[1]); mma16816(c1, ah, bh[2], bh[3]);
                mma16816(c0, al, bh[0], bh[1]); mma16816(c1, al, bh[2], bh[3]);
                mma16816(c0, ah, bl[0], bl[1]); mma16816(c1, ah, bl[2], bl[3]);
            }
        }
    }

    // ---- epilogue 2 ----
    {
        const int r0 = wr + (lane >> 2), r1 = r0 + 8;
        const int ec = 2 * (lane & 3);
        const int d0 = sDst[r0], d1 = sDst[r1];
        float* eo0 = ef_out + (size_t)(e0 + r0) * 64;
        float* eo1 = ef_out + (size_t)(e0 + r1) * 64;
        float* ag0 = g_agg + (size_t)d0 * 64;
        float* ag1 = g_agg + (size_t)d1 * 64;
        #pragma unroll
        for (int j8 = 0; j8 < 8; j8++) {
            int cb = j8 * 8 + ec;
            float be0 = sB2b[cb], be1v = sB2b[cb + 1];
            float ba0 = sB2b[64 + cb], ba1v = sB2b[64 + cb + 1];
            float ex0 = acc2[j8*4+0] + be0, ex1 = acc2[j8*4+1] + be1v;
            float ax0 = acc2[32 + j8*4+0] + ba0, ax1 = acc2[32 + j8*4+1] + ba1v;
            float m0 = ex0 / (1.f + __expf(-ax0));
            float m1 = ex1 / (1.f + __expf(-ax1));
            *(float2*)(eo0 + cb) = make_float2(m0, m1);
            red2(ag0 + cb, m0, m1);
            float ey0 = acc2[j8*4+2] + be0, ey1 = acc2[j8*4+3] + be1v;
            float ay0 = acc2[32 + j8*4+2] + ba0, ay1 = acc2[32 + j8*4+3] + ba1v;
            float n0 = ey0 / (1.f + __expf(-ay0));
            float n1 = ey1 / (1.f + __expf(-ay1));
            *(float2*)(eo1 + cb) = make_float2(n0, n1);
            red2(ag1 + cb, n0, n1);
        }
    }
}

// ---------------------------------------------------------------------------
// Node kernel (HMMA, f32-acc 3-term)
// ---------------------------------------------------------------------------
#define NOFF_B1  69632
#define NOFF_W2  139264
#define NOFF_MSC 174080
#define NODE_SMEM 174848

__global__ __launch_bounds__(256, 1) void node_kernel(
    const float* __restrict__ nf,
    const float* __restrict__ bn1, const float* __restrict__ bn2,
    float* __restrict__ nf_out)
{
    extern __shared__ char smc[];
    const uint32_t smb = smem_u32(smc);
    const int tid = threadIdx.x, wid = tid >> 5, lane = tid & 31;
    const int m0 = blockIdx.x * 128;
    float* sB1b = (float*)(smc + NOFF_MSC);
    float* sB2b = (float*)(smc + NOFF_MSC + 512);

    #pragma unroll
    for (int i = 0; i < 17; i++)
        cpa16(smb + NOFF_B1 + (tid + 256 * i) * 16, (const char*)g_Wn1 + (tid + 256 * i) * 16);
    #pragma unroll
    for (int i = 0; i < 9; i++) {
        int idx = tid + 256 * i;
        if (idx < 2176) cpa16(smb + NOFF_W2 + idx * 16, (const char*)g_Wn2 + idx * 16);
    }
    CP_COMMIT();

    if (tid < 32) ((float4*)sB1b)[tid] = ((const float4*)bn1)[tid];
    else if (tid < 48) ((float4*)sB2b)[tid - 32] = ((const float4*)bn2)[tid - 32];

    {
        const int m = tid >> 1, h = tid & 1;
        const int node = m0 + m;
        const float4* src = (h == 0) ? (const float4*)(g_agg + (size_t)node * 64)
                                     : (const float4*)(nf + (size_t)node * 64);
        #pragma unroll
        for (int it = 0; it < 16; it++) {
            float4 v = (node < NN) ? src[it] : make_float4(0.f, 0.f, 0.f, 0.f);
            int k = h * 64 + it * 4;
            uint32_t h0 = packh2(v.x, v.y), h1 = packh2(v.z, v.w);
            float2 f0 = unpackh2(h0), f1 = unpackh2(h1);
            uint32_t l0 = packh2(v.x - f0.x, v.y - f0.y), l1 = packh2(v.z - f1.x, v.w - f1.y);
            *(uint2*)(smc + 0     + m * 272 + k * 2) = make_uint2(h0, h1);
            *(uint2*)(smc + 34816 + m * 272 + k * 2) = make_uint2(l0, l1);
        }
    }
    CP_WAIT0();
    __syncthreads();

    const int wr = wid * 16;
    const uint32_t aH = smb + (uint32_t)((wr + (lane & 15)) * 272 + ((lane >> 4) * 8) * 2);
    const uint32_t aL = aH + 34816;
    const uint32_t bln = (uint32_t)((((lane >> 4) << 3) + (lane & 7)) * 272 + (((lane >> 3) & 1) ? 16 : 0));

    float acc[64];
    #pragma unroll
    for (int i = 0; i < 64; i++) acc[i] = 0.f;
    {
        const uint32_t bH = smb + NOFF_B1 + bln;
        const uint32_t bL = bH + 34816;
        #pragma unroll
        for (int ks = 0; ks < 8; ks++) {
            uint32_t ah[4], al[4];
            ldsm4(ah, aH + ks * 32);
            ldsm4(al, aL + ks * 32);
            #pragma unroll
            for (int j2 = 0; j2 < 8; j2++) {
                uint32_t bh[4], bl[4];
                ldsm4(bh, bH + j2 * 4352 + ks * 32);
                ldsm4(bl, bL + j2 * 4352 + ks * 32);
                float* c0 = &acc[(2*j2+0)*4];
                float* c1 = &acc[(2*j2+1)*4];
                mma16816(c0, ah, bh[0], bh[1]); mma16816(c1, ah, bh[2], bh[3]);
                mma16816(c0, al, bh[0], bh[1]); mma16816(c1, al, bh[2], bh[3]);
                mma16816(c0, ah, bl[0], bl[1]); mma16816(c1, ah, bl[2], bl[3]);
            }
        }
    }

    uint32_t hH[32], hL[32];
    {
        const int ec = 2 * (lane & 3);
        #pragma unroll
        for (int j8 = 0; j8 < 16; j8++) {
            int cb = 8 * j8 + ec;
            float b0 = sB1b[cb], b1 = sB1b[cb + 1];
            float v0 = fmaxf(acc[4*j8+0] + b0, 0.f);
            float v1 = fmaxf(acc[4*j8+1] + b1, 0.f);
            float v2 = fmaxf(acc[4*j8+2] + b0, 0.f);
            float v3 = fmaxf(acc[4*j8+3] + b1, 0.f);
            uint32_t h01 = packh2(v0, v1);
            float2 f01 = unpackh2(h01);
            uint32_t l01 = packh2(v0 - f01.x, v1 - f01.y);
            uint32_t h23 = packh2(v2, v3);
            float2 f23 = unpackh2(h23);
            uint32_t l23 = packh2(v2 - f23.x, v3 - f23.y);
            hH[2*j8] = h01; hL[2*j8] = l01;
            hH[2*j8+1] = h23; hL[2*j8+1] = l23;
        }
    }

    float acc2[32];
    #pragma unroll
    for (int i = 0; i < 32; i++) acc2[i] = 0.f;
    {
        const uint32_t wb = smb + NOFF_W2 + bln;
        #pragma unroll
        for (int kc = 0; kc < 8; kc++) {
            uint32_t ah[4] = { hH[4*kc], hH[4*kc+1], hH[4*kc+2], hH[4*kc+3] };
            uint32_t al[4] = { hL[4*kc], hL[4*kc+1], hL[4*kc+2], hL[4*kc+3] };
            #pragma unroll
            for (int j2 = 0; j2 < 4; j2++) {
                uint32_t bh[4], bl[4];
                ldsm4(bh, wb + j2 * 4352 + kc * 32);
                ldsm4(bl, wb + 17408 + j2 * 4352 + kc * 32);
                float* c0 = &acc2[(2*j2+0)*4];
                float* c1 = &acc2[(2*j2+1)*4];
                mma16816(c0, ah, bh[0], bh[1]); mma16816(c1, ah, bh[2], bh[3]);
                mma16816(c0, al, bh[0], bh[1]); mma16816(c1, al, bh[2], bh[3]);
                mma16816(c0, ah, bl[0], bl[1]); mma16816(c1, ah, bl[2], bl[3]);
            }
        }
    }

    {
        const int r0 = wr + (lane >> 2);
        const int ec = 2 * (lane & 3);
        const int n0 = m0 + r0, n1 = n0 + 8;
        #pragma unroll
        for (int j8 = 0; j8 < 8; j8++) {
            int cb = 8 * j8 + ec;
            float b0 = sB2b[cb], b1 = sB2b[cb + 1];
            if (n0 < NN)
                *(float2*)(nf_out + (size_t)n0 * 64 + cb) =
                    make_float2(acc2[4*j8+0] + b0, acc2[4*j8+1] + b1);
            if (n1 < NN)
                *(float2*)(nf_out + (size_t)n1 * 64 + cb) =
                    make_float2(acc2[4*j8+2] + b0, acc2[4*j8+3] + b1);
        }
    }
}

// ---------------------------------------------------------------------------
extern "C" void kernel_launch(void* const* d_in, const int* in_sizes, int n_in,
                              void* d_out, int out_size)
{
    const float* nf  = (const float*)d_in[0];
    const float* ef  = (const float*)d_in[1];
    const float* We1 = (const float*)d_in[4];
    const float* be1 = (const float*)d_in[5];
    const float* We2 = (const float*)d_in[6];
    const float* be2 = (const float*)d_in[7];
    const float* Wa1 = (const float*)d_in[8];
    const float* ba1 = (const float*)d_in[9];
    const float* Wa2 = (const float*)d_in[10];
    const float* ba2 = (const float*)d_in[11];
    const float* Wn1 = (const float*)d_in[12];
    const float* bn1 = (const float*)d_in[13];
    const float* Wn2 = (const float*)d_in[14];
    const float* bn2 = (const float*)d_in[15];

    float* nf_out = (float*)d_out;
    float* ef_out = nf_out + (size_t)NN * 64;

    cudaFuncSetAttribute(prep_P_kernel, cudaFuncAttributeMaxDynamicSharedMemorySize, PREP_SMEM);
    cudaFuncSetAttribute(edge_kernel, cudaFuncAttributeMaxDynamicSharedMemorySize, EDGE_SMEM);
    cudaFuncSetAttribute(node_kernel, cudaFuncAttributeMaxDynamicSharedMemorySize, NODE_SMEM);

    prep_all<<<3830, 256>>>((const unsigned int*)d_in[2], We1, Wa1, We2, Wa2, Wn1, Wn2);
    prep_P_kernel<<<391, 256, PREP_SMEM>>>(nf);
    edge_kernel<<<E_EDGES / 64, 128, EDGE_SMEM>>>(
        ef, (const int*)d_in[2], (const int*)d_in[3],
        be1, ba1, be2, ba2, ef_out);
    node_kernel<<<391, 256, NODE_SMEM>>>(nf, bn1, bn2, nf_out);
}

// round 14
// speedup vs baseline: 1.2516x; 1.0602x over previous
#include <cuda_runtime.h>
#include <cuda_fp16.h>
#include <math.h>
#include <stdint.h>

#define E_EDGES 800000
#define NN      50000
typedef unsigned long long ull;

__device__ int    g_idx64;
__device__ float  g_agg[(size_t)NN * 64];
__device__ float  g_P[(size_t)50048 * 512];   // [node][ P_src(256) | P_dst(256) ]
__device__ __half g_B1e[2 * 256 * 72];        // ef-part W1: [hi|lo][256 n][72 kpad] (lo unused)
__device__ __half g_BP[2 * 512 * 72];         // P-prep W1:  [hi|lo][512 n][72 kpad]
__device__ __half g_W2[2 * 2 * 64 * 136];     // [gate][hi|lo][64 n][136 kpad] (lo unused)
__device__ __half g_Wn1[2 * 128 * 136];       // node W1: [hi|lo][128 n][136 kpad]
__device__ __half g_Wn2[2 * 64 * 136];        // node W2: [hi|lo][64 n][136 kpad]

// ---------------- helpers ----------------------------------------------------
__device__ __forceinline__ uint32_t smem_u32(const void* p) {
    uint32_t a;
    asm("{ .reg .u64 t; cvta.to.shared.u64 t, %1; cvt.u32.u64 %0, t; }" : "=r"(a) : "l"(p));
    return a;
}
__device__ __forceinline__ void ldsm4(uint32_t* r, uint32_t addr) {
    asm volatile("ldmatrix.sync.aligned.m8n8.x4.shared.b16 {%0,%1,%2,%3}, [%4];"
                 : "=r"(r[0]), "=r"(r[1]), "=r"(r[2]), "=r"(r[3]) : "r"(addr));
}
__device__ __forceinline__ void mma16816(float* c, const uint32_t* a, uint32_t b0, uint32_t b1) {
    asm volatile("mma.sync.aligned.m16n8k16.row.col.f32.f16.f16.f32 "
                 "{%0,%1,%2,%3}, {%4,%5,%6,%7}, {%8,%9}, {%0,%1,%2,%3};"
                 : "+f"(c[0]), "+f"(c[1]), "+f"(c[2]), "+f"(c[3])
                 : "r"(a[0]), "r"(a[1]), "r"(a[2]), "r"(a[3]), "r"(b0), "r"(b1));
}
__device__ __forceinline__ void cpa16(uint32_t dst, const void* src) {
    asm volatile("cp.async.cg.shared.global [%0], [%1], 16;" :: "r"(dst), "l"(src));
}
#define CP_COMMIT() asm volatile("cp.async.commit_group;" ::: "memory")
#define CP_WAIT0()  asm volatile("cp.async.wait_group 0;" ::: "memory")
#define CP_WAIT1()  asm volatile("cp.async.wait_group 1;" ::: "memory")
__device__ __forceinline__ void red2(float* p, float x, float y) {
    asm volatile("red.global.add.v2.f32 [%0], {%1,%2};" :: "l"(p), "f"(x), "f"(y) : "memory");
}
__device__ __forceinline__ uint32_t packh2(float x, float y) {
    __half2 h = __floats2half2_rn(x, y);
    return *(uint32_t*)&h;
}
__device__ __forceinline__ float2 unpackh2(uint32_t u) {
    return __half22float2(*(__half2*)&u);
}

// ---------------------------------------------------------------------------
// prep_all: fused zero+detect+all weight preps (one launch).
// ---------------------------------------------------------------------------
__global__ void prep_all(const unsigned int* __restrict__ raw,
                         const float* __restrict__ We1, const float* __restrict__ Wa1,
                         const float* __restrict__ We2, const float* __restrict__ Wa2,
                         const float* __restrict__ Wn1, const float* __restrict__ Wn2)
{
    const int b = blockIdx.x, t = threadIdx.x;
    if (b < 3125) {
        ((float4*)g_agg)[b * 256 + t] = make_float4(0.f, 0.f, 0.f, 0.f);
    } else if (b == 3125) {
        __shared__ int any;
        if (t == 0) any = 0;
        __syncthreads();
        int f = 0;
        for (int i = t; i < 2048; i += blockDim.x)
            if (raw[2 * i + 1] != 0u) f = 1;
        if (f) atomicExch(&any, 1);
        __syncthreads();
        if (t == 0) g_idx64 = (any == 0) ? 1 : 0;
    } else if (b < 3254) {
        int gi = (b - 3126) * 256 + t;              // 32768
        int p = gi >> 14, r = gi & 16383;
        int n = r >> 6, kk = r & 63;
        int k = 128 + kk;
        float w = (n < 128) ? We1[k * 128 + n] : Wa1[k * 128 + (n - 128)];
        __half hi = __float2half_rn(w);
        __half v = (p == 0) ? hi : __float2half_rn(w - __half2float(hi));
        g_B1e[(p * 256 + n) * 72 + kk] = v;
    } else if (b < 3382) {
        int gi = (b - 3254) * 256 + t;              // 32768
        int g = gi >> 14, p = (gi >> 13) & 1;
        int r = gi & 8191, n = r >> 7, k = r & 127;
        const float* W = g ? Wa2 : We2;
        float w = W[k * 64 + n];
        __half hi = __float2half_rn(w);
        __half v = (p == 0) ? hi : __float2half_rn(w - __half2float(hi));
        g_W2[((g * 2 + p) * 64 + n) * 136 + k] = v;
    } else if (b < 3638) {
        int gi = (b - 3382) * 256 + t;              // 65536
        int p = gi >> 15, r = gi & 32767;
        int nIdx = r >> 6, kk = r & 63;
        int part = nIdx >> 8, c = nIdx & 255;
        int k = part * 64 + kk;
        float w = (c < 128) ? We1[k * 128 + c] : Wa1[k * 128 + (c - 128)];
        __half hi = __float2half_rn(w);
        __half v = (p == 0) ? hi : __float2half_rn(w - __half2float(hi));
        g_BP[(p * 512 + nIdx) * 72 + kk] = v;
    } else if (b < 3766) {
        int gi = (b - 3638) * 256 + t;              // 32768
        int p = gi >> 14, r = gi & 16383;
        int n = r >> 7, k = r & 127;
        float w = Wn1[k * 128 + n];
        __half hi = __float2half_rn(w);
        __half v = (p == 0) ? hi : __float2half_rn(w - __half2float(hi));
        g_Wn1[(p * 128 + n) * 136 + k] = v;
    } else {
        int gi = (b - 3766) * 256 + t;              // 16384
        int p = gi >> 13, r = gi & 8191;
        int n = r >> 7, k = r & 127;
        float w = Wn2[k * 64 + n];
        __half hi = __float2half_rn(w);
        __half v = (p == 0) ? hi : __float2half_rn(w - __half2float(hi));
        g_Wn2[(p * 64 + n) * 136 + k] = v;
    }
}

// ---------------------------------------------------------------------------
// prep_P: P[n][512] = nf[n] @ [W_src | W_dst], split-fp16 3-term HMMA.
// ---------------------------------------------------------------------------
#define PREP_SMEM 184320
__global__ __launch_bounds__(256, 1) void prep_P_kernel(const float* __restrict__ nf)
{
    extern __shared__ char smc[];
    const uint32_t smb = smem_u32(smc);
    const int tid = threadIdx.x, wid = tid >> 5, lane = tid & 31;
    const int m0 = blockIdx.x * 128;

    #pragma unroll
    for (int i = 0; i < 36; i++)
        cpa16(smb + 36864 + (tid + 256 * i) * 16, (const char*)g_BP + (tid + 256 * i) * 16);
    CP_COMMIT();

    {
        const int m = tid >> 1, h = tid & 1;
        const int node = m0 + m;
        const float* row = nf + (size_t)node * 64;
        #pragma unroll
        for (int it = 0; it < 8; it++) {
            int q = h * 8 + it;
            float4 v = (node < NN) ? ((const float4*)row)[q] : make_float4(0.f, 0.f, 0.f, 0.f);
            uint32_t h0 = packh2(v.x, v.y), h1 = packh2(v.z, v.w);
            float2 f0 = unpackh2(h0), f1 = unpackh2(h1);
            uint32_t l0 = packh2(v.x - f0.x, v.y - f0.y), l1 = packh2(v.z - f1.x, v.w - f1.y);
            *(uint2*)(smc + 0     + m * 144 + q * 8) = make_uint2(h0, h1);
            *(uint2*)(smc + 18432 + m * 144 + q * 8) = make_uint2(l0, l1);
        }
    }
    CP_WAIT0();
    __syncthreads();

    const int wr = wid * 16;
    const uint32_t aH = smb + (uint32_t)((wr + (lane & 15)) * 144 + ((lane >> 4) * 8) * 2);
    const uint32_t aL = aH + 18432;
    const uint32_t bln = (uint32_t)((((lane >> 4) << 3) + (lane & 7)) * 144 + (((lane >> 3) & 1) ? 16 : 0));
    const int r0 = wr + (lane >> 2);
    const int ec = 2 * (lane & 3);

    #pragma unroll
    for (int p = 0; p < 2; p++) {
        float acc[128];
        #pragma unroll
        for (int i = 0; i < 128; i++) acc[i] = 0.f;
        const uint32_t bH = smb + 36864  + (uint32_t)(p * 36864) + bln;
        const uint32_t bL = bH + 73728;
        #pragma unroll
        for (int ks = 0; ks < 4; ks++) {
            uint32_t ah[4], al[4];
            ldsm4(ah, aH + ks * 32);
            ldsm4(al, aL + ks * 32);
            #pragma unroll
            for (int j2 = 0; j2 < 16; j2++) {
                uint32_t bh[4], bl[4];
                ldsm4(bh, bH + j2 * 2304 + ks * 32);
                ldsm4(bl, bL + j2 * 2304 + ks * 32);
                mma16816(&acc[(2*j2+0)*4], ah, bh[0], bh[1]); mma16816(&acc[(2*j2+1)*4], ah, bh[2], bh[3]);
                mma16816(&acc[(2*j2+0)*4], al, bh[0], bh[1]); mma16816(&acc[(2*j2+1)*4], al, bh[2], bh[3]);
                mma16816(&acc[(2*j2+0)*4], ah, bl[0], bl[1]); mma16816(&acc[(2*j2+1)*4], ah, bl[2], bl[3]);
            }
        }
        #pragma unroll
        for (int j8 = 0; j8 < 32; j8++) {
            int cb = p * 256 + 8 * j8 + ec;
            *(float2*)(g_P + (size_t)(m0 + r0) * 512 + cb)     = make_float2(acc[4*j8+0], acc[4*j8+1]);
            *(float2*)(g_P + (size_t)(m0 + r0 + 8) * 512 + cb) = make_float2(acc[4*j8+2], acc[4*j8+3]);
        }
    }
}

// ---------------------------------------------------------------------------
// Edge kernel, occ-3. GEMM1: plain fp16 (K=64). GEMM2: plain fp16 (K=128/gate).
// ---------------------------------------------------------------------------
#define OFF_A1H  0
#define OFF_B1A  18432
#define OFF_B1B  36864
#define OFF_MISC 69632
#define EDGE_SMEM 71680
#define PSTR 260

__global__ __launch_bounds__(128, 3) void edge_kernel(
    const float* __restrict__ ef,
    const int* __restrict__ rawsrc, const int* __restrict__ rawdst,
    const float* __restrict__ be1, const float* __restrict__ ba1,
    const float* __restrict__ be2, const float* __restrict__ ba2,
    float* __restrict__ ef_out)
{
    extern __shared__ char smc[];
    const uint32_t smb = smem_u32(smc);
    const int tid = threadIdx.x, wid = tid >> 5, lane = tid & 31;
    const int e0 = blockIdx.x * 64;

    int*   sSrc  = (int*)(smc + OFF_MISC);
    int*   sDst  = (int*)(smc + OFF_MISC + 256);
    float* sBias = (float*)(smc + OFF_MISC + 512);
    float* sB2b  = (float*)(smc + OFF_MISC + 1536);
    float* sPs   = (float*)(smc);

    // B1 hi: both n-chunks preloaded
    #pragma unroll
    for (int i = 0; i < 9; i++)
        cpa16(smb + OFF_B1A + (tid + 128 * i) * 16, (const char*)g_B1e + (tid + 128 * i) * 16);
    CP_COMMIT();
    #pragma unroll
    for (int i = 0; i < 9; i++)
        cpa16(smb + OFF_B1B + (tid + 128 * i) * 16, (const char*)g_B1e + 18432 + (tid + 128 * i) * 16);
    CP_COMMIT();

    const int is64 = g_idx64;
    if (tid < 64) sSrc[tid] = is64 ? rawsrc[2 * (e0 + tid)] : rawsrc[e0 + tid];
    else { int m = tid - 64; sDst[m] = is64 ? rawdst[2 * (e0 + m)] : rawdst[e0 + m]; }
    if (tid < 64)
        ((float4*)sBias)[tid] = (tid < 32) ? ((const float4*)be1)[tid] : ((const float4*)ba1)[tid - 32];
    else if (tid < 96)
        ((float4*)sB2b)[tid - 64] = (tid < 80) ? ((const float4*)be2)[tid - 64] : ((const float4*)ba2)[tid - 80];

    // gather ef rows -> fp16 (hi only)
    {
        const int m = tid >> 1, h = tid & 1;
        const float* row = ef + (size_t)(e0 + m) * 64;
        #pragma unroll
        for (int it = 0; it < 8; it++) {
            int q = h * 8 + it;
            float4 v = ((const float4*)row)[q];
            uint32_t h0 = packh2(v.x, v.y), h1 = packh2(v.z, v.w);
            *(uint2*)(smc + OFF_A1H + m * 144 + q * 8) = make_uint2(h0, h1);
        }
    }

    const int wr = wid * 16;
    const uint32_t aH = smb + OFF_A1H + (uint32_t)((wr + (lane & 15)) * 144 + ((lane >> 4) * 8) * 2);
    const uint32_t bln = (uint32_t)((((lane >> 4) << 3) + (lane & 7)) * 144 + (((lane >> 3) & 1) ? 16 : 0));

    float acc[128];
    #pragma unroll
    for (int i = 0; i < 128; i++) acc[i] = 0.f;

    // ---- GEMM1: 2 stages {Wh n0-127, Wh n128-255}, plain fp16 ----
    #pragma unroll
    for (int s = 0; s < 2; s++) {
        if (s == 0) { CP_WAIT1(); } else { CP_WAIT0(); }
        __syncthreads();
        const uint32_t bB = smb + (s ? OFF_B1B : OFF_B1A) + bln;
        const int jbase = s * 8;
        #pragma unroll
        for (int ks = 0; ks < 4; ks++) {
            uint32_t ah[4];
            ldsm4(ah, aH + ks * 32);
            #pragma unroll
            for (int j2l = 0; j2l < 8; j2l++) {
                uint32_t bh[4];
                ldsm4(bh, bB + j2l * 2304 + ks * 32);
                int j2 = jbase + j2l;
                mma16816(&acc[(2*j2+0)*4], ah, bh[0], bh[1]);
                mma16816(&acc[(2*j2+1)*4], ah, bh[2], bh[3]);
            }
        }
    }
    __syncthreads();
    // A1/B1 dead. Gather Psum into [0, 66560).

    // ---- P gather: Psum[m][..] = P_src[src[m]] + P_dst[dst[m]][256:] ----
    {
        #pragma unroll
        for (int it = 0; it < 16; it++) {
            int m = (wid << 4) + it;
            const float4* ps = (const float4*)(g_P + (size_t)sSrc[m] * 512);
            const float4* pd = (const float4*)(g_P + (size_t)sDst[m] * 512 + 256);
            #pragma unroll
            for (int j = 0; j < 2; j++) {
                int f4 = lane + 32 * j;
                float4 a = ps[f4], b = pd[f4];
                *(float4*)(sPs + m * PSTR + f4 * 4) =
                    make_float4(a.x + b.x, a.y + b.y, a.z + b.z, a.w + b.w);
            }
        }
    }
    __syncthreads();

    // ---- epilogue 1: H = relu(acc + Psum + bias) -> fp16 hi regs only ----
    uint32_t hH[64];
    {
        const int r0 = wr + (lane >> 2);
        const int ec = 2 * (lane & 3);
        #pragma unroll
        for (int j8 = 0; j8 < 32; j8++) {
            int cb = 8 * j8 + ec;
            float2 p0 = *(float2*)(sPs + r0 * PSTR + cb);
            float2 p1v = *(float2*)(sPs + (r0 + 8) * PSTR + cb);
            float b0 = sBias[cb], b1 = sBias[cb + 1];
            float v0 = fmaxf(acc[4*j8+0] + p0.x + b0, 0.f);
            float v1 = fmaxf(acc[4*j8+1] + p0.y + b1, 0.f);
            float v2 = fmaxf(acc[4*j8+2] + p1v.x + b0, 0.f);
            float v3 = fmaxf(acc[4*j8+3] + p1v.y + b1, 0.f);
            hH[2*j8]   = packh2(v0, v1);
            hH[2*j8+1] = packh2(v2, v3);
        }
    }
    __syncthreads();   // Psum reads done -> region reusable for W2

    // ---- stage W2 hi only: e-gate @0 (17408), a-gate @17408 (17408) ----
    #pragma unroll
    for (int i = 0; i < 9; i++) {
        int idx = tid + 128 * i;
        if (idx < 1088) cpa16(smb + idx * 16, (const char*)g_W2 + idx * 16);
    }
    CP_COMMIT();
    #pragma unroll
    for (int i = 0; i < 9; i++) {
        int idx = tid + 128 * i;
        if (idx < 1088) cpa16(smb + 17408 + idx * 16, (const char*)g_W2 + 34816 + idx * 16);
    }
    CP_COMMIT();
    CP_WAIT1();        // e-gate ready
    __syncthreads();

    // ---- GEMM2: plain fp16. hf=0: H_e (cols 0-127) @ We2; hf=1: H_a @ Wa2 ----
    const uint32_t w2ln = (uint32_t)((((lane >> 4) << 3) + (lane & 7)) * 272 + (((lane >> 3) & 1) ? 16 : 0));
    float acc2[64];
    #pragma unroll
    for (int i = 0; i < 64; i++) acc2[i] = 0.f;

    #pragma unroll
    for (int hf = 0; hf < 2; hf++) {
        if (hf == 1) { CP_WAIT0(); __syncthreads(); }
        const uint32_t wb = smb + (uint32_t)(hf * 17408) + w2ln;
        #pragma unroll
        for (int kc = 0; kc < 8; kc++) {
            int jb = hf * 32 + 4 * kc;   // FIX: gate a reads H columns 128-255
            uint32_t ah[4] = { hH[jb], hH[jb+1], hH[jb+2], hH[jb+3] };
            #pragma unroll
            for (int j2 = 0; j2 < 4; j2++) {
                uint32_t bh[4];
                ldsm4(bh, wb + j2 * 4352 + kc * 32);
                float* c0 = &acc2[hf * 32 + (2*j2+0) * 4];
                float* c1 = &acc2[hf * 32 + (2*j2+1) * 4];
                mma16816(c0, ah, bh[0], bh[1]);
                mma16816(c1, ah, bh[2], bh[3]);
            }
        }
    }

    // ---- epilogue 2 ----
    {
        const int r0 = wr + (lane >> 2), r1 = r0 + 8;
        const int ec = 2 * (lane & 3);
        const int d0 = sDst[r0], d1 = sDst[r1];
        float* eo0 = ef_out + (size_t)(e0 + r0) * 64;
        float* eo1 = ef_out + (size_t)(e0 + r1) * 64;
        float* ag0 = g_agg + (size_t)d0 * 64;
        float* ag1 = g_agg + (size_t)d1 * 64;
        #pragma unroll
        for (int j8 = 0; j8 < 8; j8++) {
            int cb = j8 * 8 + ec;
            float be0 = sB2b[cb], be1v = sB2b[cb + 1];
            float ba0 = sB2b[64 + cb], ba1v = sB2b[64 + cb + 1];
            float ex0 = acc2[j8*4+0] + be0, ex1 = acc2[j8*4+1] + be1v;
            float ax0 = acc2[32 + j8*4+0] + ba0, ax1 = acc2[32 + j8*4+1] + ba1v;
            float m0 = ex0 / (1.f + __expf(-ax0));
            float m1 = ex1 / (1.f + __expf(-ax1));
            *(float2*)(eo0 + cb) = make_float2(m0, m1);
            red2(ag0 + cb, m0, m1);
            float ey0 = acc2[j8*4+2] + be0, ey1 = acc2[j8*4+3] + be1v;
            float ay0 = acc2[32 + j8*4+2] + ba0, ay1 = acc2[32 + j8*4+3] + ba1v;
            float n0 = ey0 / (1.f + __expf(-ay0));
            float n1 = ey1 / (1.f + __expf(-ay1));
            *(float2*)(eo1 + cb) = make_float2(n0, n1);
            red2(ag1 + cb, n0, n1);
        }
    }
}

// ---------------------------------------------------------------------------
// Node kernel (HMMA, f32-acc 3-term)
// ---------------------------------------------------------------------------
#define NOFF_B1  69632
#define NOFF_W2  139264
#define NOFF_MSC 174080
#define NODE_SMEM 174848

__global__ __launch_bounds__(256, 1) void node_kernel(
    const float* __restrict__ nf,
    const float* __restrict__ bn1, const float* __restrict__ bn2,
    float* __restrict__ nf_out)
{
    extern __shared__ char smc[];
    const uint32_t smb = smem_u32(smc);
    const int tid = threadIdx.x, wid = tid >> 5, lane = tid & 31;
    const int m0 = blockIdx.x * 128;
    float* sB1b = (float*)(smc + NOFF_MSC);
    float* sB2b = (float*)(smc + NOFF_MSC + 512);

    #pragma unroll
    for (int i = 0; i < 17; i++)
        cpa16(smb + NOFF_B1 + (tid + 256 * i) * 16, (const char*)g_Wn1 + (tid + 256 * i) * 16);
    #pragma unroll
    for (int i = 0; i < 9; i++) {
        int idx = tid + 256 * i;
        if (idx < 2176) cpa16(smb + NOFF_W2 + idx * 16, (const char*)g_Wn2 + idx * 16);
    }
    CP_COMMIT();

    if (tid < 32) ((float4*)sB1b)[tid] = ((const float4*)bn1)[tid];
    else if (tid < 48) ((float4*)sB2b)[tid - 32] = ((const float4*)bn2)[tid - 32];

    {
        const int m = tid >> 1, h = tid & 1;
        const int node = m0 + m;
        const float4* src = (h == 0) ? (const float4*)(g_agg + (size_t)node * 64)
                                     : (const float4*)(nf + (size_t)node * 64);
        #pragma unroll
        for (int it = 0; it < 16; it++) {
            float4 v = (node < NN) ? src[it] : make_float4(0.f, 0.f, 0.f, 0.f);
            int k = h * 64 + it * 4;
            uint32_t h0 = packh2(v.x, v.y), h1 = packh2(v.z, v.w);
            float2 f0 = unpackh2(h0), f1 = unpackh2(h1);
            uint32_t l0 = packh2(v.x - f0.x, v.y - f0.y), l1 = packh2(v.z - f1.x, v.w - f1.y);
            *(uint2*)(smc + 0     + m * 272 + k * 2) = make_uint2(h0, h1);
            *(uint2*)(smc + 34816 + m * 272 + k * 2) = make_uint2(l0, l1);
        }
    }
    CP_WAIT0();
    __syncthreads();

    const int wr = wid * 16;
    const uint32_t aH = smb + (uint32_t)((wr + (lane & 15)) * 272 + ((lane >> 4) * 8) * 2);
    const uint32_t aL = aH + 34816;
    const uint32_t bln = (uint32_t)((((lane >> 4) << 3) + (lane & 7)) * 272 + (((lane >> 3) & 1) ? 16 : 0));

    float acc[64];
    #pragma unroll
    for (int i = 0; i < 64; i++) acc[i] = 0.f;
    {
        const uint32_t bH = smb + NOFF_B1 + bln;
        const uint32_t bL = bH + 34816;
        #pragma unroll
        for (int ks = 0; ks < 8; ks++) {
            uint32_t ah[4], al[4];
            ldsm4(ah, aH + ks * 32);
            ldsm4(al, aL + ks * 32);
            #pragma unroll
            for (int j2 = 0; j2 < 8; j2++) {
                uint32_t bh[4], bl[4];
                ldsm4(bh, bH + j2 * 4352 + ks * 32);
                ldsm4(bl, bL + j2 * 4352 + ks * 32);
                float* c0 = &acc[(2*j2+0)*4];
                float* c1 = &acc[(2*j2+1)*4];
                mma16816(c0, ah, bh[0], bh[1]); mma16816(c1, ah, bh[2], bh[3]);
                mma16816(c0, al, bh[0], bh[1]); mma16816(c1, al, bh[2], bh[3]);
                mma16816(c0, ah, bl[0], bl[1]); mma16816(c1, ah, bl[2], bl[3]);
            }
        }
    }

    uint32_t hH[32], hL[32];
    {
        const int ec = 2 * (lane & 3);
        #pragma unroll
        for (int j8 = 0; j8 < 16; j8++) {
            int cb = 8 * j8 + ec;
            float b0 = sB1b[cb], b1 = sB1b[cb + 1];
            float v0 = fmaxf(acc[4*j8+0] + b0, 0.f);
            float v1 = fmaxf(acc[4*j8+1] + b1, 0.f);
            float v2 = fmaxf(acc[4*j8+2] + b0, 0.f);
            float v3 = fmaxf(acc[4*j8+3] + b1, 0.f);
            uint32_t h01 = packh2(v0, v1);
            float2 f01 = unpackh2(h01);
            uint32_t l01 = packh2(v0 - f01.x, v1 - f01.y);
            uint32_t h23 = packh2(v2, v3);
            float2 f23 = unpackh2(h23);
            uint32_t l23 = packh2(v2 - f23.x, v3 - f23.y);
            hH[2*j8] = h01; hL[2*j8] = l01;
            hH[2*j8+1] = h23; hL[2*j8+1] = l23;
        }
    }

    float acc2[32];
    #pragma unroll
    for (int i = 0; i < 32; i++) acc2[i] = 0.f;
    {
        const uint32_t wb = smb + NOFF_W2 + bln;
        #pragma unroll
        for (int kc = 0; kc < 8; kc++) {
            uint32_t ah[4] = { hH[4*kc], hH[4*kc+1], hH[4*kc+2], hH[4*kc+3] };
            uint32_t al[4] = { hL[4*kc], hL[4*kc+1], hL[4*kc+2], hL[4*kc+3] };
            #pragma unroll
            for (int j2 = 0; j2 < 4; j2++) {
                uint32_t bh[4], bl[4];
                ldsm4(bh, wb + j2 * 4352 + kc * 32);
                ldsm4(bl, wb + 17408 + j2 * 4352 + kc * 32);
                float* c0 = &acc2[(2*j2+0)*4];
                float* c1 = &acc2[(2*j2+1)*4];
                mma16816(c0, ah, bh[0], bh[1]); mma16816(c1, ah, bh[2], bh[3]);
                mma16816(c0, al, bh[0], bh[1]); mma16816(c1, al, bh[2], bh[3]);
                mma16816(c0, ah, bl[0], bl[1]); mma16816(c1, ah, bl[2], bl[3]);
            }
        }
    }

    {
        const int r0 = wr + (lane >> 2);
        const int ec = 2 * (lane & 3);
        const int n0 = m0 + r0, n1 = n0 + 8;
        #pragma unroll
        for (int j8 = 0; j8 < 8; j8++) {
            int cb = 8 * j8 + ec;
            float b0 = sB2b[cb], b1 = sB2b[cb + 1];
            if (n0 < NN)
                *(float2*)(nf_out + (size_t)n0 * 64 + cb) =
                    make_float2(acc2[4*j8+0] + b0, acc2[4*j8+1] + b1);
            if (n1 < NN)
                *(float2*)(nf_out + (size_t)n1 * 64 + cb) =
                    make_float2(acc2[4*j8+2] + b0, acc2[4*j8+3] + b1);
        }
    }
}

// ---------------------------------------------------------------------------
extern "C" void kernel_launch(void* const* d_in, const int* in_sizes, int n_in,
                              void* d_out, int out_size)
{
    const float* nf  = (const float*)d_in[0];
    const float* ef  = (const float*)d_in[1];
    const float* We1 = (const float*)d_in[4];
    const float* be1 = (const float*)d_in[5];
    const float* We2 = (const float*)d_in[6];
    const float* be2 = (const float*)d_in[7];
    const float* Wa1 = (const float*)d_in[8];
    const float* ba1 = (const float*)d_in[9];
    const float* Wa2 = (const float*)d_in[10];
    const float* ba2 = (const float*)d_in[11];
    const float* Wn1 = (const float*)d_in[12];
    const float* bn1 = (const float*)d_in[13];
    const float* Wn2 = (const float*)d_in[14];
    const float* bn2 = (const float*)d_in[15];

    float* nf_out = (float*)d_out;
    float* ef_out = nf_out + (size_t)NN * 64;

    cudaFuncSetAttribute(prep_P_kernel, cudaFuncAttributeMaxDynamicSharedMemorySize, PREP_SMEM);
    cudaFuncSetAttribute(edge_kernel, cudaFuncAttributeMaxDynamicSharedMemorySize, EDGE_SMEM);
    cudaFuncSetAttribute(node_kernel, cudaFuncAttributeMaxDynamicSharedMemorySize, NODE_SMEM);

    prep_all<<<3830, 256>>>((const unsigned int*)d_in[2], We1, Wa1, We2, Wa2, Wn1, Wn2);
    prep_P_kernel<<<391, 256, PREP_SMEM>>>(nf);
    edge_kernel<<<E_EDGES / 64, 128, EDGE_SMEM>>>(
        ef, (const int*)d_in[2], (const int*)d_in[3],
        be1, ba1, be2, ba2, ef_out);
    node_kernel<<<391, 256, NODE_SMEM>>>(nf, bn1, bn2, nf_out);
}

// round 15
// speedup vs baseline: 1.3252x; 1.0588x over previous
#include <cuda_runtime.h>
#include <cuda_fp16.h>
#include <math.h>
#include <stdint.h>

#define E_EDGES 800000
#define NN      50000
typedef unsigned long long ull;

__device__ int    g_idx64;
__device__ float  g_agg[(size_t)NN * 64];
__device__ __half g_P[(size_t)50048 * 512];   // fp16: [node][ P_src(256) | P_dst(256) ]
__device__ __half g_B1e[2 * 256 * 72];        // ef-part W1: [hi|lo][256 n][72 kpad] (lo unused)
__device__ __half g_BP[2 * 512 * 72];         // P-prep W1:  [hi|lo][512 n][72 kpad]
__device__ __half g_W2[2 * 2 * 64 * 136];     // [gate][hi|lo][64 n][136 kpad] (lo unused)
__device__ __half g_Wn1[2 * 128 * 136];       // node W1: [hi|lo][128 n][136 kpad]
__device__ __half g_Wn2[2 * 64 * 136];        // node W2: [hi|lo][64 n][136 kpad]

// ---------------- helpers ----------------------------------------------------
__device__ __forceinline__ uint32_t smem_u32(const void* p) {
    uint32_t a;
    asm("{ .reg .u64 t; cvta.to.shared.u64 t, %1; cvt.u32.u64 %0, t; }" : "=r"(a) : "l"(p));
    return a;
}
__device__ __forceinline__ void ldsm4(uint32_t* r, uint32_t addr) {
    asm volatile("ldmatrix.sync.aligned.m8n8.x4.shared.b16 {%0,%1,%2,%3}, [%4];"
                 : "=r"(r[0]), "=r"(r[1]), "=r"(r[2]), "=r"(r[3]) : "r"(addr));
}
__device__ __forceinline__ void mma16816(float* c, const uint32_t* a, uint32_t b0, uint32_t b1) {
    asm volatile("mma.sync.aligned.m16n8k16.row.col.f32.f16.f16.f32 "
                 "{%0,%1,%2,%3}, {%4,%5,%6,%7}, {%8,%9}, {%0,%1,%2,%3};"
                 : "+f"(c[0]), "+f"(c[1]), "+f"(c[2]), "+f"(c[3])
                 : "r"(a[0]), "r"(a[1]), "r"(a[2]), "r"(a[3]), "r"(b0), "r"(b1));
}
__device__ __forceinline__ void cpa16(uint32_t dst, const void* src) {
    asm volatile("cp.async.cg.shared.global [%0], [%1], 16;" :: "r"(dst), "l"(src));
}
#define CP_COMMIT() asm volatile("cp.async.commit_group;" ::: "memory")
#define CP_WAIT0()  asm volatile("cp.async.wait_group 0;" ::: "memory")
#define CP_WAIT1()  asm volatile("cp.async.wait_group 1;" ::: "memory")
__device__ __forceinline__ void red2(float* p, float x, float y) {
    asm volatile("red.global.add.v2.f32 [%0], {%1,%2};" :: "l"(p), "f"(x), "f"(y) : "memory");
}
__device__ __forceinline__ uint32_t packh2(float x, float y) {
    __half2 h = __floats2half2_rn(x, y);
    return *(uint32_t*)&h;
}
__device__ __forceinline__ float2 unpackh2(uint32_t u) {
    return __half22float2(*(__half2*)&u);
}

// ---------------------------------------------------------------------------
// prep_all: fused zero+detect+all weight preps (one launch).
// ---------------------------------------------------------------------------
__global__ void prep_all(const unsigned int* __restrict__ raw,
                         const float* __restrict__ We1, const float* __restrict__ Wa1,
                         const float* __restrict__ We2, const float* __restrict__ Wa2,
                         const float* __restrict__ Wn1, const float* __restrict__ Wn2)
{
    const int b = blockIdx.x, t = threadIdx.x;
    if (b < 3125) {
        ((float4*)g_agg)[b * 256 + t] = make_float4(0.f, 0.f, 0.f, 0.f);
    } else if (b == 3125) {
        __shared__ int any;
        if (t == 0) any = 0;
        __syncthreads();
        int f = 0;
        for (int i = t; i < 2048; i += blockDim.x)
            if (raw[2 * i + 1] != 0u) f = 1;
        if (f) atomicExch(&any, 1);
        __syncthreads();
        if (t == 0) g_idx64 = (any == 0) ? 1 : 0;
    } else if (b < 3254) {
        int gi = (b - 3126) * 256 + t;              // 32768
        int p = gi >> 14, r = gi & 16383;
        int n = r >> 6, kk = r & 63;
        int k = 128 + kk;
        float w = (n < 128) ? We1[k * 128 + n] : Wa1[k * 128 + (n - 128)];
        __half hi = __float2half_rn(w);
        __half v = (p == 0) ? hi : __float2half_rn(w - __half2float(hi));
        g_B1e[(p * 256 + n) * 72 + kk] = v;
    } else if (b < 3382) {
        int gi = (b - 3254) * 256 + t;              // 32768
        int g = gi >> 14, p = (gi >> 13) & 1;
        int r = gi & 8191, n = r >> 7, k = r & 127;
        const float* W = g ? Wa2 : We2;
        float w = W[k * 64 + n];
        __half hi = __float2half_rn(w);
        __half v = (p == 0) ? hi : __float2half_rn(w - __half2float(hi));
        g_W2[((g * 2 + p) * 64 + n) * 136 + k] = v;
    } else if (b < 3638) {
        int gi = (b - 3382) * 256 + t;              // 65536
        int p = gi >> 15, r = gi & 32767;
        int nIdx = r >> 6, kk = r & 63;
        int part = nIdx >> 8, c = nIdx & 255;
        int k = part * 64 + kk;
        float w = (c < 128) ? We1[k * 128 + c] : Wa1[k * 128 + (c - 128)];
        __half hi = __float2half_rn(w);
        __half v = (p == 0) ? hi : __float2half_rn(w - __half2float(hi));
        g_BP[(p * 512 + nIdx) * 72 + kk] = v;
    } else if (b < 3766) {
        int gi = (b - 3638) * 256 + t;              // 32768
        int p = gi >> 14, r = gi & 16383;
        int n = r >> 7, k = r & 127;
        float w = Wn1[k * 128 + n];
        __half hi = __float2half_rn(w);
        __half v = (p == 0) ? hi : __float2half_rn(w - __half2float(hi));
        g_Wn1[(p * 128 + n) * 136 + k] = v;
    } else {
        int gi = (b - 3766) * 256 + t;              // 16384
        int p = gi >> 13, r = gi & 8191;
        int n = r >> 7, k = r & 127;
        float w = Wn2[k * 64 + n];
        __half hi = __float2half_rn(w);
        __half v = (p == 0) ? hi : __float2half_rn(w - __half2float(hi));
        g_Wn2[(p * 64 + n) * 136 + k] = v;
    }
}

// ---------------------------------------------------------------------------
// prep_P: P[n][512] = nf[n] @ [W_src | W_dst], split-fp16 3-term HMMA.
// Output stored as fp16 (halves gather traffic; g_P becomes L2-resident).
// ---------------------------------------------------------------------------
#define PREP_SMEM 184320
__global__ __launch_bounds__(256, 1) void prep_P_kernel(const float* __restrict__ nf)
{
    extern __shared__ char smc[];
    const uint32_t smb = smem_u32(smc);
    const int tid = threadIdx.x, wid = tid >> 5, lane = tid & 31;
    const int m0 = blockIdx.x * 128;

    #pragma unroll
    for (int i = 0; i < 36; i++)
        cpa16(smb + 36864 + (tid + 256 * i) * 16, (const char*)g_BP + (tid + 256 * i) * 16);
    CP_COMMIT();

    {
        const int m = tid >> 1, h = tid & 1;
        const int node = m0 + m;
        const float* row = nf + (size_t)node * 64;
        #pragma unroll
        for (int it = 0; it < 8; it++) {
            int q = h * 8 + it;
            float4 v = (node < NN) ? ((const float4*)row)[q] : make_float4(0.f, 0.f, 0.f, 0.f);
            uint32_t h0 = packh2(v.x, v.y), h1 = packh2(v.z, v.w);
            float2 f0 = unpackh2(h0), f1 = unpackh2(h1);
            uint32_t l0 = packh2(v.x - f0.x, v.y - f0.y), l1 = packh2(v.z - f1.x, v.w - f1.y);
            *(uint2*)(smc + 0     + m * 144 + q * 8) = make_uint2(h0, h1);
            *(uint2*)(smc + 18432 + m * 144 + q * 8) = make_uint2(l0, l1);
        }
    }
    CP_WAIT0();
    __syncthreads();

    const int wr = wid * 16;
    const uint32_t aH = smb + (uint32_t)((wr + (lane & 15)) * 144 + ((lane >> 4) * 8) * 2);
    const uint32_t aL = aH + 18432;
    const uint32_t bln = (uint32_t)((((lane >> 4) << 3) + (lane & 7)) * 144 + (((lane >> 3) & 1) ? 16 : 0));
    const int r0 = wr + (lane >> 2);
    const int ec = 2 * (lane & 3);

    #pragma unroll
    for (int p = 0; p < 2; p++) {
        float acc[128];
        #pragma unroll
        for (int i = 0; i < 128; i++) acc[i] = 0.f;
        const uint32_t bH = smb + 36864  + (uint32_t)(p * 36864) + bln;
        const uint32_t bL = bH + 73728;
        #pragma unroll
        for (int ks = 0; ks < 4; ks++) {
            uint32_t ah[4], al[4];
            ldsm4(ah, aH + ks * 32);
            ldsm4(al, aL + ks * 32);
            #pragma unroll
            for (int j2 = 0; j2 < 16; j2++) {
                uint32_t bh[4], bl[4];
                ldsm4(bh, bH + j2 * 2304 + ks * 32);
                ldsm4(bl, bL + j2 * 2304 + ks * 32);
                mma16816(&acc[(2*j2+0)*4], ah, bh[0], bh[1]); mma16816(&acc[(2*j2+1)*4], ah, bh[2], bh[3]);
                mma16816(&acc[(2*j2+0)*4], al, bh[0], bh[1]); mma16816(&acc[(2*j2+1)*4], al, bh[2], bh[3]);
                mma16816(&acc[(2*j2+0)*4], ah, bl[0], bl[1]); mma16816(&acc[(2*j2+1)*4], ah, bl[2], bl[3]);
            }
        }
        #pragma unroll
        for (int j8 = 0; j8 < 32; j8++) {
            int cb = p * 256 + 8 * j8 + ec;
            *(uint32_t*)((char*)g_P + ((size_t)(m0 + r0) * 512 + cb) * 2)     = packh2(acc[4*j8+0], acc[4*j8+1]);
            *(uint32_t*)((char*)g_P + ((size_t)(m0 + r0 + 8) * 512 + cb) * 2) = packh2(acc[4*j8+2], acc[4*j8+3]);
        }
    }
}

// ---------------------------------------------------------------------------
// Edge kernel, occ-3. GEMM1: plain fp16 (K=64). GEMM2: plain fp16 (K=128/gate).
// P gather now fp16 (half the L2 bytes).
// ---------------------------------------------------------------------------
#define OFF_A1H  0
#define OFF_B1A  18432
#define OFF_B1B  36864
#define OFF_MISC 69632
#define EDGE_SMEM 71680
#define PSTR 260

__global__ __launch_bounds__(128, 3) void edge_kernel(
    const float* __restrict__ ef,
    const int* __restrict__ rawsrc, const int* __restrict__ rawdst,
    const float* __restrict__ be1, const float* __restrict__ ba1,
    const float* __restrict__ be2, const float* __restrict__ ba2,
    float* __restrict__ ef_out)
{
    extern __shared__ char smc[];
    const uint32_t smb = smem_u32(smc);
    const int tid = threadIdx.x, wid = tid >> 5, lane = tid & 31;
    const int e0 = blockIdx.x * 64;

    int*   sSrc  = (int*)(smc + OFF_MISC);
    int*   sDst  = (int*)(smc + OFF_MISC + 256);
    float* sBias = (float*)(smc + OFF_MISC + 512);
    float* sB2b  = (float*)(smc + OFF_MISC + 1536);
    float* sPs   = (float*)(smc);

    // B1 hi: both n-chunks preloaded
    #pragma unroll
    for (int i = 0; i < 9; i++)
        cpa16(smb + OFF_B1A + (tid + 128 * i) * 16, (const char*)g_B1e + (tid + 128 * i) * 16);
    CP_COMMIT();
    #pragma unroll
    for (int i = 0; i < 9; i++)
        cpa16(smb + OFF_B1B + (tid + 128 * i) * 16, (const char*)g_B1e + 18432 + (tid + 128 * i) * 16);
    CP_COMMIT();

    const int is64 = g_idx64;
    if (tid < 64) sSrc[tid] = is64 ? rawsrc[2 * (e0 + tid)] : rawsrc[e0 + tid];
    else { int m = tid - 64; sDst[m] = is64 ? rawdst[2 * (e0 + m)] : rawdst[e0 + m]; }
    if (tid < 64)
        ((float4*)sBias)[tid] = (tid < 32) ? ((const float4*)be1)[tid] : ((const float4*)ba1)[tid - 32];
    else if (tid < 96)
        ((float4*)sB2b)[tid - 64] = (tid < 80) ? ((const float4*)be2)[tid - 64] : ((const float4*)ba2)[tid - 80];

    // gather ef rows -> fp16 (hi only)
    {
        const int m = tid >> 1, h = tid & 1;
        const float* row = ef + (size_t)(e0 + m) * 64;
        #pragma unroll
        for (int it = 0; it < 8; it++) {
            int q = h * 8 + it;
            float4 v = ((const float4*)row)[q];
            uint32_t h0 = packh2(v.x, v.y), h1 = packh2(v.z, v.w);
            *(uint2*)(smc + OFF_A1H + m * 144 + q * 8) = make_uint2(h0, h1);
        }
    }

    const int wr = wid * 16;
    const uint32_t aH = smb + OFF_A1H + (uint32_t)((wr + (lane & 15)) * 144 + ((lane >> 4) * 8) * 2);
    const uint32_t bln = (uint32_t)((((lane >> 4) << 3) + (lane & 7)) * 144 + (((lane >> 3) & 1) ? 16 : 0));

    float acc[128];
    #pragma unroll
    for (int i = 0; i < 128; i++) acc[i] = 0.f;

    // ---- GEMM1: 2 stages {Wh n0-127, Wh n128-255}, plain fp16 ----
    #pragma unroll
    for (int s = 0; s < 2; s++) {
        if (s == 0) { CP_WAIT1(); } else { CP_WAIT0(); }
        __syncthreads();
        const uint32_t bB = smb + (s ? OFF_B1B : OFF_B1A) + bln;
        const int jbase = s * 8;
        #pragma unroll
        for (int ks = 0; ks < 4; ks++) {
            uint32_t ah[4];
            ldsm4(ah, aH + ks * 32);
            #pragma unroll
            for (int j2l = 0; j2l < 8; j2l++) {
                uint32_t bh[4];
                ldsm4(bh, bB + j2l * 2304 + ks * 32);
                int j2 = jbase + j2l;
                mma16816(&acc[(2*j2+0)*4], ah, bh[0], bh[1]);
                mma16816(&acc[(2*j2+1)*4], ah, bh[2], bh[3]);
            }
        }
    }
    __syncthreads();
    // A1/B1 dead. Gather Psum into [0, 66560).

    // ---- P gather (fp16): Psum[m][..] = P_src[src[m]] + P_dst[dst[m]][256:] ----
    {
        #pragma unroll
        for (int it = 0; it < 16; it++) {
            int m = (wid << 4) + it;
            const uint4* ps = (const uint4*)(g_P + (size_t)sSrc[m] * 512);          // 256 halves = 32 uint4
            const uint4* pd = (const uint4*)(g_P + (size_t)sDst[m] * 512 + 256);
            uint4 a = ps[lane], b = pd[lane];
            float2 a0 = unpackh2(a.x), a1 = unpackh2(a.y), a2 = unpackh2(a.z), a3 = unpackh2(a.w);
            float2 b0 = unpackh2(b.x), b1 = unpackh2(b.y), b2 = unpackh2(b.z), b3 = unpackh2(b.w);
            float* dst = sPs + m * PSTR + lane * 8;
            *(float4*)(dst)     = make_float4(a0.x + b0.x, a0.y + b0.y, a1.x + b1.x, a1.y + b1.y);
            *(float4*)(dst + 4) = make_float4(a2.x + b2.x, a2.y + b2.y, a3.x + b3.x, a3.y + b3.y);
        }
    }
    __syncthreads();

    // ---- epilogue 1: H = relu(acc + Psum + bias) -> fp16 hi regs only ----
    uint32_t hH[64];
    {
        const int r0 = wr + (lane >> 2);
        const int ec = 2 * (lane & 3);
        #pragma unroll
        for (int j8 = 0; j8 < 32; j8++) {
            int cb = 8 * j8 + ec;
            float2 p0 = *(float2*)(sPs + r0 * PSTR + cb);
            float2 p1v = *(float2*)(sPs + (r0 + 8) * PSTR + cb);
            float b0 = sBias[cb], b1 = sBias[cb + 1];
            float v0 = fmaxf(acc[4*j8+0] + p0.x + b0, 0.f);
            float v1 = fmaxf(acc[4*j8+1] + p0.y + b1, 0.f);
            float v2 = fmaxf(acc[4*j8+2] + p1v.x + b0, 0.f);
            float v3 = fmaxf(acc[4*j8+3] + p1v.y + b1, 0.f);
            hH[2*j8]   = packh2(v0, v1);
            hH[2*j8+1] = packh2(v2, v3);
        }
    }
    __syncthreads();   // Psum reads done -> region reusable for W2

    // ---- stage W2 hi only: e-gate @0 (17408), a-gate @17408 (17408) ----
    #pragma unroll
    for (int i = 0; i < 9; i++) {
        int idx = tid + 128 * i;
        if (idx < 1088) cpa16(smb + idx * 16, (const char*)g_W2 + idx * 16);
    }
    CP_COMMIT();
    #pragma unroll
    for (int i = 0; i < 9; i++) {
        int idx = tid + 128 * i;
        if (idx < 1088) cpa16(smb + 17408 + idx * 16, (const char*)g_W2 + 34816 + idx * 16);
    }
    CP_COMMIT();
    CP_WAIT1();        // e-gate ready
    __syncthreads();

    // ---- GEMM2: plain fp16. hf=0: H_e (cols 0-127) @ We2; hf=1: H_a @ Wa2 ----
    const uint32_t w2ln = (uint32_t)((((lane >> 4) << 3) + (lane & 7)) * 272 + (((lane >> 3) & 1) ? 16 : 0));
    float acc2[64];
    #pragma unroll
    for (int i = 0; i < 64; i++) acc2[i] = 0.f;

    #pragma unroll
    for (int hf = 0; hf < 2; hf++) {
        if (hf == 1) { CP_WAIT0(); __syncthreads(); }
        const uint32_t wb = smb + (uint32_t)(hf * 17408) + w2ln;
        #pragma unroll
        for (int kc = 0; kc < 8; kc++) {
            int jb = hf * 32 + 4 * kc;   // gate a reads H columns 128-255
            uint32_t ah[4] = { hH[jb], hH[jb+1], hH[jb+2], hH[jb+3] };
            #pragma unroll
            for (int j2 = 0; j2 < 4; j2++) {
                uint32_t bh[4];
                ldsm4(bh, wb + j2 * 4352 + kc * 32);
                float* c0 = &acc2[hf * 32 + (2*j2+0) * 4];
                float* c1 = &acc2[hf * 32 + (2*j2+1) * 4];
                mma16816(c0, ah, bh[0], bh[1]);
                mma16816(c1, ah, bh[2], bh[3]);
            }
        }
    }

    // ---- epilogue 2 ----
    {
        const int r0 = wr + (lane >> 2), r1 = r0 + 8;
        const int ec = 2 * (lane & 3);
        const int d0 = sDst[r0], d1 = sDst[r1];
        float* eo0 = ef_out + (size_t)(e0 + r0) * 64;
        float* eo1 = ef_out + (size_t)(e0 + r1) * 64;
        float* ag0 = g_agg + (size_t)d0 * 64;
        float* ag1 = g_agg + (size_t)d1 * 64;
        #pragma unroll
        for (int j8 = 0; j8 < 8; j8++) {
            int cb = j8 * 8 + ec;
            float be0 = sB2b[cb], be1v = sB2b[cb + 1];
            float ba0 = sB2b[64 + cb], ba1v = sB2b[64 + cb + 1];
            float ex0 = acc2[j8*4+0] + be0, ex1 = acc2[j8*4+1] + be1v;
            float ax0 = acc2[32 + j8*4+0] + ba0, ax1 = acc2[32 + j8*4+1] + ba1v;
            float m0 = ex0 / (1.f + __expf(-ax0));
            float m1 = ex1 / (1.f + __expf(-ax1));
            *(float2*)(eo0 + cb) = make_float2(m0, m1);
            red2(ag0 + cb, m0, m1);
            float ey0 = acc2[j8*4+2] + be0, ey1 = acc2[j8*4+3] + be1v;
            float ay0 = acc2[32 + j8*4+2] + ba0, ay1 = acc2[32 + j8*4+3] + ba1v;
            float n0 = ey0 / (1.f + __expf(-ay0));
            float n1 = ey1 / (1.f + __expf(-ay1));
            *(float2*)(eo1 + cb) = make_float2(n0, n1);
            red2(ag1 + cb, n0, n1);
        }
    }
}

// ---------------------------------------------------------------------------
// Node kernel (HMMA, f32-acc 3-term)
// ---------------------------------------------------------------------------
#define NOFF_B1  69632
#define NOFF_W2  139264
#define NOFF_MSC 174080
#define NODE_SMEM 174848

__global__ __launch_bounds__(256, 1) void node_kernel(
    const float* __restrict__ nf,
    const float* __restrict__ bn1, const float* __restrict__ bn2,
    float* __restrict__ nf_out)
{
    extern __shared__ char smc[];
    const uint32_t smb = smem_u32(smc);
    const int tid = threadIdx.x, wid = tid >> 5, lane = tid & 31;
    const int m0 = blockIdx.x * 128;
    float* sB1b = (float*)(smc + NOFF_MSC);
    float* sB2b = (float*)(smc + NOFF_MSC + 512);

    #pragma unroll
    for (int i = 0; i < 17; i++)
        cpa16(smb + NOFF_B1 + (tid + 256 * i) * 16, (const char*)g_Wn1 + (tid + 256 * i) * 16);
    #pragma unroll
    for (int i = 0; i < 9; i++) {
        int idx = tid + 256 * i;
        if (idx < 2176) cpa16(smb + NOFF_W2 + idx * 16, (const char*)g_Wn2 + idx * 16);
    }
    CP_COMMIT();

    if (tid < 32) ((float4*)sB1b)[tid] = ((const float4*)bn1)[tid];
    else if (tid < 48) ((float4*)sB2b)[tid - 32] = ((const float4*)bn2)[tid - 32];

    {
        const int m = tid >> 1, h = tid & 1;
        const int node = m0 + m;
        const float4* src = (h == 0) ? (const float4*)(g_agg + (size_t)node * 64)
                                     : (const float4*)(nf + (size_t)node * 64);
        #pragma unroll
        for (int it = 0; it < 16; it++) {
            float4 v = (node < NN) ? src[it] : make_float4(0.f, 0.f, 0.f, 0.f);
            int k = h * 64 + it * 4;
            uint32_t h0 = packh2(v.x, v.y), h1 = packh2(v.z, v.w);
            float2 f0 = unpackh2(h0), f1 = unpackh2(h1);
            uint32_t l0 = packh2(v.x - f0.x, v.y - f0.y), l1 = packh2(v.z - f1.x, v.w - f1.y);
            *(uint2*)(smc + 0     + m * 272 + k * 2) = make_uint2(h0, h1);
            *(uint2*)(smc + 34816 + m * 272 + k * 2) = make_uint2(l0, l1);
        }
    }
    CP_WAIT0();
    __syncthreads();

    const int wr = wid * 16;
    const uint32_t aH = smb + (uint32_t)((wr + (lane & 15)) * 272 + ((lane >> 4) * 8) * 2);
    const uint32_t aL = aH + 34816;
    const uint32_t bln = (uint32_t)((((lane >> 4) << 3) + (lane & 7)) * 272 + (((lane >> 3) & 1) ? 16 : 0));

    float acc[64];
    #pragma unroll
    for (int i = 0; i < 64; i++) acc[i] = 0.f;
    {
        const uint32_t bH = smb + NOFF_B1 + bln;
        const uint32_t bL = bH + 34816;
        #pragma unroll
        for (int ks = 0; ks < 8; ks++) {
            uint32_t ah[4], al[4];
            ldsm4(ah, aH + ks * 32);
            ldsm4(al, aL + ks * 32);
            #pragma unroll
            for (int j2 = 0; j2 < 8; j2++) {
                uint32_t bh[4], bl[4];
                ldsm4(bh, bH + j2 * 4352 + ks * 32);
                ldsm4(bl, bL + j2 * 4352 + ks * 32);
                float* c0 = &acc[(2*j2+0)*4];
                float* c1 = &acc[(2*j2+1)*4];
                mma16816(c0, ah, bh[0], bh[1]); mma16816(c1, ah, bh[2], bh[3]);
                mma16816(c0, al, bh[0], bh[1]); mma16816(c1, al, bh[2], bh[3]);
                mma16816(c0, ah, bl[0], bl[1]); mma16816(c1, ah, bl[2], bl[3]);
            }
        }
    }

    uint32_t hH[32], hL[32];
    {
        const int ec = 2 * (lane & 3);
        #pragma unroll
        for (int j8 = 0; j8 < 16; j8++) {
            int cb = 8 * j8 + ec;
            float b0 = sB1b[cb], b1 = sB1b[cb + 1];
            float v0 = fmaxf(acc[4*j8+0] + b0, 0.f);
            float v1 = fmaxf(acc[4*j8+1] + b1, 0.f);
            float v2 = fmaxf(acc[4*j8+2] + b0, 0.f);
            float v3 = fmaxf(acc[4*j8+3] + b1, 0.f);
            uint32_t h01 = packh2(v0, v1);
            float2 f01 = unpackh2(h01);
            uint32_t l01 = packh2(v0 - f01.x, v1 - f01.y);
            uint32_t h23 = packh2(v2, v3);
            float2 f23 = unpackh2(h23);
            uint32_t l23 = packh2(v2 - f23.x, v3 - f23.y);
            hH[2*j8] = h01; hL[2*j8] = l01;
            hH[2*j8+1] = h23; hL[2*j8+1] = l23;
        }
    }

    float acc2[32];
    #pragma unroll
    for (int i = 0; i < 32; i++) acc2[i] = 0.f;
    {
        const uint32_t wb = smb + NOFF_W2 + bln;
        #pragma unroll
        for (int kc = 0; kc < 8; kc++) {
            uint32_t ah[4] = { hH[4*kc], hH[4*kc+1], hH[4*kc+2], hH[4*kc+3] };
            uint32_t al[4] = { hL[4*kc], hL[4*kc+1], hL[4*kc+2], hL[4*kc+3] };
            #pragma unroll
            for (int j2 = 0; j2 < 4; j2++) {
                uint32_t bh[4], bl[4];
                ldsm4(bh, wb + j2 * 4352 + kc * 32);
                ldsm4(bl, wb + 17408 + j2 * 4352 + kc * 32);
                float* c0 = &acc2[(2*j2+0)*4];
                float* c1 = &acc2[(2*j2+1)*4];
                mma16816(c0, ah, bh[0], bh[1]); mma16816(c1, ah, bh[2], bh[3]);
                mma16816(c0, al, bh[0], bh[1]); mma16816(c1, al, bh[2], bh[3]);
                mma16816(c0, ah, bl[0], bl[1]); mma16816(c1, ah, bl[2], bl[3]);
            }
        }
    }

    {
        const int r0 = wr + (lane >> 2);
        const int ec = 2 * (lane & 3);
        const int n0 = m0 + r0, n1 = n0 + 8;
        #pragma unroll
        for (int j8 = 0; j8 < 8; j8++) {
            int cb = 8 * j8 + ec;
            float b0 = sB2b[cb], b1 = sB2b[cb + 1];
            if (n0 < NN)
                *(float2*)(nf_out + (size_t)n0 * 64 + cb) =
                    make_float2(acc2[4*j8+0] + b0, acc2[4*j8+1] + b1);
            if (n1 < NN)
                *(float2*)(nf_out + (size_t)n1 * 64 + cb) =
                    make_float2(acc2[4*j8+2] + b0, acc2[4*j8+3] + b1);
        }
    }
}

// ---------------------------------------------------------------------------
extern "C" void kernel_launch(void* const* d_in, const int* in_sizes, int n_in,
                              void* d_out, int out_size)
{
    const float* nf  = (const float*)d_in[0];
    const float* ef  = (const float*)d_in[1];
    const float* We1 = (const float*)d_in[4];
    const float* be1 = (const float*)d_in[5];
    const float* We2 = (const float*)d_in[6];
    const float* be2 = (const float*)d_in[7];
    const float* Wa1 = (const float*)d_in[8];
    const float* ba1 = (const float*)d_in[9];
    const float* Wa2 = (const float*)d_in[10];
    const float* ba2 = (const float*)d_in[11];
    const float* Wn1 = (const float*)d_in[12];
    const float* bn1 = (const float*)d_in[13];
    const float* Wn2 = (const float*)d_in[14];
    const float* bn2 = (const float*)d_in[15];

    float* nf_out = (float*)d_out;
    float* ef_out = nf_out + (size_t)NN * 64;

    cudaFuncSetAttribute(prep_P_kernel, cudaFuncAttributeMaxDynamicSharedMemorySize, PREP_SMEM);
    cudaFuncSetAttribute(edge_kernel, cudaFuncAttributeMaxDynamicSharedMemorySize, EDGE_SMEM);
    cudaFuncSetAttribute(node_kernel, cudaFuncAttributeMaxDynamicSharedMemorySize, NODE_SMEM);

    prep_all<<<3830, 256>>>((const unsigned int*)d_in[2], We1, Wa1, We2, Wa2, Wn1, Wn2);
    prep_P_kernel<<<391, 256, PREP_SMEM>>>(nf);
    edge_kernel<<<E_EDGES / 64, 128, EDGE_SMEM>>>(
        ef, (const int*)d_in[2], (const int*)d_in[3],
        be1, ba1, be2, ba2, ef_out);
    node_kernel<<<391, 256, NODE_SMEM>>>(nf, bn1, bn2, nf_out);
}

// round 16
// speedup vs baseline: 1.5871x; 1.1977x over previous
#include <cuda_runtime.h>
#include <cuda_fp16.h>
#include <math.h>
#include <stdint.h>

#define E_EDGES 800000
#define NN      50000
typedef unsigned long long ull;

__device__ int    g_idx64;
__device__ float  g_agg[(size_t)NN * 64];
__device__ __half g_P[(size_t)50048 * 512];   // fp16: [node][ P_src(256) | P_dst(256) ]
__device__ __half g_B1e[2 * 256 * 72];        // ef-part W1: [hi|lo][256 n][72 kpad] (lo unused)
__device__ __half g_BP[2 * 512 * 72];         // P-prep W1:  [hi|lo][512 n][72 kpad]
__device__ __half g_W2[2 * 2 * 64 * 136];     // [gate][hi|lo][64 n][136 kpad] (lo unused)
__device__ __half g_Wn1[2 * 128 * 136];       // node W1: [hi|lo][128 n][136 kpad]
__device__ __half g_Wn2[2 * 64 * 136];        // node W2: [hi|lo][64 n][136 kpad]

// ---------------- helpers ----------------------------------------------------
__device__ __forceinline__ uint32_t smem_u32(const void* p) {
    uint32_t a;
    asm("{ .reg .u64 t; cvta.to.shared.u64 t, %1; cvt.u32.u64 %0, t; }" : "=r"(a) : "l"(p));
    return a;
}
__device__ __forceinline__ void ldsm4(uint32_t* r, uint32_t addr) {
    asm volatile("ldmatrix.sync.aligned.m8n8.x4.shared.b16 {%0,%1,%2,%3}, [%4];"
                 : "=r"(r[0]), "=r"(r[1]), "=r"(r[2]), "=r"(r[3]) : "r"(addr));
}
__device__ __forceinline__ void mma16816(float* c, const uint32_t* a, uint32_t b0, uint32_t b1) {
    asm volatile("mma.sync.aligned.m16n8k16.row.col.f32.f16.f16.f32 "
                 "{%0,%1,%2,%3}, {%4,%5,%6,%7}, {%8,%9}, {%0,%1,%2,%3};"
                 : "+f"(c[0]), "+f"(c[1]), "+f"(c[2]), "+f"(c[3])
                 : "r"(a[0]), "r"(a[1]), "r"(a[2]), "r"(a[3]), "r"(b0), "r"(b1));
}
__device__ __forceinline__ void cpa16(uint32_t dst, const void* src) {
    asm volatile("cp.async.cg.shared.global [%0], [%1], 16;" :: "r"(dst), "l"(src));
}
#define CP_COMMIT() asm volatile("cp.async.commit_group;" ::: "memory")
#define CP_WAIT0()  asm volatile("cp.async.wait_group 0;" ::: "memory")
#define CP_WAIT1()  asm volatile("cp.async.wait_group 1;" ::: "memory")
__device__ __forceinline__ void red2(float* p, float x, float y) {
    asm volatile("red.global.add.v2.f32 [%0], {%1,%2};" :: "l"(p), "f"(x), "f"(y) : "memory");
}
__device__ __forceinline__ uint32_t packh2(float x, float y) {
    __half2 h = __floats2half2_rn(x, y);
    return *(uint32_t*)&h;
}
__device__ __forceinline__ float2 unpackh2(uint32_t u) {
    return __half22float2(*(__half2*)&u);
}

// ---------------------------------------------------------------------------
// prep_all: fused zero+detect+all weight preps (one launch).
// ---------------------------------------------------------------------------
__global__ void prep_all(const unsigned int* __restrict__ raw,
                         const float* __restrict__ We1, const float* __restrict__ Wa1,
                         const float* __restrict__ We2, const float* __restrict__ Wa2,
                         const float* __restrict__ Wn1, const float* __restrict__ Wn2)
{
    const int b = blockIdx.x, t = threadIdx.x;
    if (b < 3125) {
        ((float4*)g_agg)[b * 256 + t] = make_float4(0.f, 0.f, 0.f, 0.f);
    } else if (b == 3125) {
        __shared__ int any;
        if (t == 0) any = 0;
        __syncthreads();
        int f = 0;
        for (int i = t; i < 2048; i += blockDim.x)
            if (raw[2 * i + 1] != 0u) f = 1;
        if (f) atomicExch(&any, 1);
        __syncthreads();
        if (t == 0) g_idx64 = (any == 0) ? 1 : 0;
    } else if (b < 3254) {
        int gi = (b - 3126) * 256 + t;              // 32768
        int p = gi >> 14, r = gi & 16383;
        int n = r >> 6, kk = r & 63;
        int k = 128 + kk;
        float w = (n < 128) ? We1[k * 128 + n] : Wa1[k * 128 + (n - 128)];
        __half hi = __float2half_rn(w);
        __half v = (p == 0) ? hi : __float2half_rn(w - __half2float(hi));
        g_B1e[(p * 256 + n) * 72 + kk] = v;
    } else if (b < 3382) {
        int gi = (b - 3254) * 256 + t;              // 32768
        int g = gi >> 14, p = (gi >> 13) & 1;
        int r = gi & 8191, n = r >> 7, k = r & 127;
        const float* W = g ? Wa2 : We2;
        float w = W[k * 64 + n];
        __half hi = __float2half_rn(w);
        __half v = (p == 0) ? hi : __float2half_rn(w - __half2float(hi));
        g_W2[((g * 2 + p) * 64 + n) * 136 + k] = v;
    } else if (b < 3638) {
        int gi = (b - 3382) * 256 + t;              // 65536
        int p = gi >> 15, r = gi & 32767;
        int nIdx = r >> 6, kk = r & 63;
        int part = nIdx >> 8, c = nIdx & 255;
        int k = part * 64 + kk;
        float w = (c < 128) ? We1[k * 128 + c] : Wa1[k * 128 + (c - 128)];
        __half hi = __float2half_rn(w);
        __half v = (p == 0) ? hi : __float2half_rn(w - __half2float(hi));
        g_BP[(p * 512 + nIdx) * 72 + kk] = v;
    } else if (b < 3766) {
        int gi = (b - 3638) * 256 + t;              // 32768
        int p = gi >> 14, r = gi & 16383;
        int n = r >> 7, k = r & 127;
        float w = Wn1[k * 128 + n];
        __half hi = __float2half_rn(w);
        __half v = (p == 0) ? hi : __float2half_rn(w - __half2float(hi));
        g_Wn1[(p * 128 + n) * 136 + k] = v;
    } else {
        int gi = (b - 3766) * 256 + t;              // 16384
        int p = gi >> 13, r = gi & 8191;
        int n = r >> 7, k = r & 127;
        float w = Wn2[k * 64 + n];
        __half hi = __float2half_rn(w);
        __half v = (p == 0) ? hi : __float2half_rn(w - __half2float(hi));
        g_Wn2[(p * 64 + n) * 136 + k] = v;
    }
}

// ---------------------------------------------------------------------------
// prep_P: P[n][512] = nf[n] @ [W_src | W_dst], split-fp16 3-term HMMA -> fp16.
// ---------------------------------------------------------------------------
#define PREP_SMEM 184320
__global__ __launch_bounds__(256, 1) void prep_P_kernel(const float* __restrict__ nf)
{
    extern __shared__ char smc[];
    const uint32_t smb = smem_u32(smc);
    const int tid = threadIdx.x, wid = tid >> 5, lane = tid & 31;
    const int m0 = blockIdx.x * 128;

    #pragma unroll
    for (int i = 0; i < 36; i++)
        cpa16(smb + 36864 + (tid + 256 * i) * 16, (const char*)g_BP + (tid + 256 * i) * 16);
    CP_COMMIT();

    {
        const int m = tid >> 1, h = tid & 1;
        const int node = m0 + m;
        const float* row = nf + (size_t)node * 64;
        #pragma unroll
        for (int it = 0; it < 8; it++) {
            int q = h * 8 + it;
            float4 v = (node < NN) ? ((const float4*)row)[q] : make_float4(0.f, 0.f, 0.f, 0.f);
            uint32_t h0 = packh2(v.x, v.y), h1 = packh2(v.z, v.w);
            float2 f0 = unpackh2(h0), f1 = unpackh2(h1);
            uint32_t l0 = packh2(v.x - f0.x, v.y - f0.y), l1 = packh2(v.z - f1.x, v.w - f1.y);
            *(uint2*)(smc + 0     + m * 144 + q * 8) = make_uint2(h0, h1);
            *(uint2*)(smc + 18432 + m * 144 + q * 8) = make_uint2(l0, l1);
        }
    }
    CP_WAIT0();
    __syncthreads();

    const int wr = wid * 16;
    const uint32_t aH = smb + (uint32_t)((wr + (lane & 15)) * 144 + ((lane >> 4) * 8) * 2);
    const uint32_t aL = aH + 18432;
    const uint32_t bln = (uint32_t)((((lane >> 4) << 3) + (lane & 7)) * 144 + (((lane >> 3) & 1) ? 16 : 0));
    const int r0 = wr + (lane >> 2);
    const int ec = 2 * (lane & 3);

    #pragma unroll
    for (int p = 0; p < 2; p++) {
        float acc[128];
        #pragma unroll
        for (int i = 0; i < 128; i++) acc[i] = 0.f;
        const uint32_t bH = smb + 36864  + (uint32_t)(p * 36864) + bln;
        const uint32_t bL = bH + 73728;
        #pragma unroll
        for (int ks = 0; ks < 4; ks++) {
            uint32_t ah[4], al[4];
            ldsm4(ah, aH + ks * 32);
            ldsm4(al, aL + ks * 32);
            #pragma unroll
            for (int j2 = 0; j2 < 16; j2++) {
                uint32_t bh[4], bl[4];
                ldsm4(bh, bH + j2 * 2304 + ks * 32);
                ldsm4(bl, bL + j2 * 2304 + ks * 32);
                mma16816(&acc[(2*j2+0)*4], ah, bh[0], bh[1]); mma16816(&acc[(2*j2+1)*4], ah, bh[2], bh[3]);
                mma16816(&acc[(2*j2+0)*4], al, bh[0], bh[1]); mma16816(&acc[(2*j2+1)*4], al, bh[2], bh[3]);
                mma16816(&acc[(2*j2+0)*4], ah, bl[0], bl[1]); mma16816(&acc[(2*j2+1)*4], ah, bl[2], bl[3]);
            }
        }
        #pragma unroll
        for (int j8 = 0; j8 < 32; j8++) {
            int cb = p * 256 + 8 * j8 + ec;
            *(uint32_t*)((char*)g_P + ((size_t)(m0 + r0) * 512 + cb) * 2)     = packh2(acc[4*j8+0], acc[4*j8+1]);
            *(uint32_t*)((char*)g_P + ((size_t)(m0 + r0 + 8) * 512 + cb) * 2) = packh2(acc[4*j8+2], acc[4*j8+3]);
        }
    }
}

// ---------------------------------------------------------------------------
// Edge kernel, occ-3. SMEM map:
//  GEMM1:  A1H @0 (9216), B1A @9216 (18432), B1B @27648 (18432) -> [0,46080)
//  post-GEMM1: Psum fp16 @0 (64 x 528B = 33792) ; W2 @33792 (34816) -> 68608
//  misc @68608 (2048) -> 70656 ; 3 x 70656 = 211968 <= 227KB
//  W2 copies issue right after GEMM1 -> overlap gather + epilogue-1.
// ---------------------------------------------------------------------------
#define OFF_A1H  0
#define OFF_B1A  9216
#define OFF_B1B  27648
#define OFF_W2   33792
#define OFF_MISC 68608
#define EDGE_SMEM 70656
#define PSB 528          // Psum row stride in bytes (264 halves)

__global__ __launch_bounds__(128, 3) void edge_kernel(
    const float* __restrict__ ef,
    const int* __restrict__ rawsrc, const int* __restrict__ rawdst,
    const float* __restrict__ be1, const float* __restrict__ ba1,
    const float* __restrict__ be2, const float* __restrict__ ba2,
    float* __restrict__ ef_out)
{
    extern __shared__ char smc[];
    const uint32_t smb = smem_u32(smc);
    const int tid = threadIdx.x, wid = tid >> 5, lane = tid & 31;
    const int e0 = blockIdx.x * 64;

    int*   sSrc  = (int*)(smc + OFF_MISC);
    int*   sDst  = (int*)(smc + OFF_MISC + 256);
    float* sBias = (float*)(smc + OFF_MISC + 512);
    float* sB2b  = (float*)(smc + OFF_MISC + 1536);

    // B1 hi: both n-chunks preloaded
    #pragma unroll
    for (int i = 0; i < 9; i++)
        cpa16(smb + OFF_B1A + (tid + 128 * i) * 16, (const char*)g_B1e + (tid + 128 * i) * 16);
    CP_COMMIT();
    #pragma unroll
    for (int i = 0; i < 9; i++)
        cpa16(smb + OFF_B1B + (tid + 128 * i) * 16, (const char*)g_B1e + 18432 + (tid + 128 * i) * 16);
    CP_COMMIT();

    const int is64 = g_idx64;
    if (tid < 64) sSrc[tid] = is64 ? rawsrc[2 * (e0 + tid)] : rawsrc[e0 + tid];
    else { int m = tid - 64; sDst[m] = is64 ? rawdst[2 * (e0 + m)] : rawdst[e0 + m]; }
    if (tid < 64)
        ((float4*)sBias)[tid] = (tid < 32) ? ((const float4*)be1)[tid] : ((const float4*)ba1)[tid - 32];
    else if (tid < 96)
        ((float4*)sB2b)[tid - 64] = (tid < 80) ? ((const float4*)be2)[tid - 64] : ((const float4*)ba2)[tid - 80];

    // gather ef rows -> fp16 (hi only)
    {
        const int m = tid >> 1, h = tid & 1;
        const float* row = ef + (size_t)(e0 + m) * 64;
        #pragma unroll
        for (int it = 0; it < 8; it++) {
            int q = h * 8 + it;
            float4 v = ((const float4*)row)[q];
            uint32_t h0 = packh2(v.x, v.y), h1 = packh2(v.z, v.w);
            *(uint2*)(smc + OFF_A1H + m * 144 + q * 8) = make_uint2(h0, h1);
        }
    }

    const int wr = wid * 16;
    const uint32_t aH = smb + OFF_A1H + (uint32_t)((wr + (lane & 15)) * 144 + ((lane >> 4) * 8) * 2);
    const uint32_t bln = (uint32_t)((((lane >> 4) << 3) + (lane & 7)) * 144 + (((lane >> 3) & 1) ? 16 : 0));

    float acc[128];
    #pragma unroll
    for (int i = 0; i < 128; i++) acc[i] = 0.f;

    // ---- GEMM1: 2 stages {Wh n0-127, Wh n128-255}, plain fp16 ----
    #pragma unroll
    for (int s = 0; s < 2; s++) {
        if (s == 0) { CP_WAIT1(); } else { CP_WAIT0(); }
        __syncthreads();
        const uint32_t bB = smb + (s ? OFF_B1B : OFF_B1A) + bln;
        const int jbase = s * 8;
        #pragma unroll
        for (int ks = 0; ks < 4; ks++) {
            uint32_t ah[4];
            ldsm4(ah, aH + ks * 32);
            #pragma unroll
            for (int j2l = 0; j2l < 8; j2l++) {
                uint32_t bh[4];
                ldsm4(bh, bB + j2l * 2304 + ks * 32);
                int j2 = jbase + j2l;
                mma16816(&acc[(2*j2+0)*4], ah, bh[0], bh[1]);
                mma16816(&acc[(2*j2+1)*4], ah, bh[2], bh[3]);
            }
        }
    }
    __syncthreads();
    // A1/B1 dead. Issue W2 copies NOW (disjoint from Psum) -> overlap gather+epi1.
    #pragma unroll
    for (int i = 0; i < 9; i++) {
        int idx = tid + 128 * i;
        if (idx < 1088) cpa16(smb + OFF_W2 + idx * 16, (const char*)g_W2 + idx * 16);
    }
    CP_COMMIT();
    #pragma unroll
    for (int i = 0; i < 9; i++) {
        int idx = tid + 128 * i;
        if (idx < 1088) cpa16(smb + OFF_W2 + 17408 + idx * 16, (const char*)g_W2 + 34816 + idx * 16);
    }
    CP_COMMIT();

    // ---- P gather (fp16 in, fp16 Psum out): Psum[m] = P_src[src[m]] + P_dst[dst[m]][256:]
    {
        #pragma unroll
        for (int it = 0; it < 16; it++) {
            int m = (wid << 4) + it;
            const uint4* ps = (const uint4*)(g_P + (size_t)sSrc[m] * 512);
            const uint4* pd = (const uint4*)(g_P + (size_t)sDst[m] * 512 + 256);
            uint4 a = ps[lane], b = pd[lane];
            float2 a0 = unpackh2(a.x), a1 = unpackh2(a.y), a2 = unpackh2(a.z), a3 = unpackh2(a.w);
            float2 b0 = unpackh2(b.x), b1 = unpackh2(b.y), b2 = unpackh2(b.z), b3 = unpackh2(b.w);
            uint4 o;
            o.x = packh2(a0.x + b0.x, a0.y + b0.y);
            o.y = packh2(a1.x + b1.x, a1.y + b1.y);
            o.z = packh2(a2.x + b2.x, a2.y + b2.y);
            o.w = packh2(a3.x + b3.x, a3.y + b3.y);
            *(uint4*)(smc + m * PSB + lane * 16) = o;
        }
    }
    __syncthreads();

    // ---- epilogue 1: H = relu(acc + Psum + bias) -> fp16 hi regs only ----
    uint32_t hH[64];
    {
        const int r0 = wr + (lane >> 2);
        const int ec = 2 * (lane & 3);
        #pragma unroll
        for (int j8 = 0; j8 < 32; j8++) {
            int cb = 8 * j8 + ec;
            float2 p0 = unpackh2(*(uint32_t*)(smc + r0 * PSB + cb * 2));
            float2 p1v = unpackh2(*(uint32_t*)(smc + (r0 + 8) * PSB + cb * 2));
            float b0 = sBias[cb], b1 = sBias[cb + 1];
            float v0 = fmaxf(acc[4*j8+0] + p0.x + b0, 0.f);
            float v1 = fmaxf(acc[4*j8+1] + p0.y + b1, 0.f);
            float v2 = fmaxf(acc[4*j8+2] + p1v.x + b0, 0.f);
            float v3 = fmaxf(acc[4*j8+3] + p1v.y + b1, 0.f);
            hH[2*j8]   = packh2(v0, v1);
            hH[2*j8+1] = packh2(v2, v3);
        }
    }

    CP_WAIT1();        // e-gate W2 ready (overlapped with gather + epilogue-1)
    __syncthreads();

    // ---- GEMM2: plain fp16. hf=0: H_e @ We2; hf=1: H_a @ Wa2 ----
    const uint32_t w2ln = (uint32_t)((((lane >> 4) << 3) + (lane & 7)) * 272 + (((lane >> 3) & 1) ? 16 : 0));
    float acc2[64];
    #pragma unroll
    for (int i = 0; i < 64; i++) acc2[i] = 0.f;

    #pragma unroll
    for (int hf = 0; hf < 2; hf++) {
        if (hf == 1) { CP_WAIT0(); __syncthreads(); }
        const uint32_t wb = smb + OFF_W2 + (uint32_t)(hf * 17408) + w2ln;
        #pragma unroll
        for (int kc = 0; kc < 8; kc++) {
            int jb = hf * 32 + 4 * kc;   // gate a reads H columns 128-255
            uint32_t ah[4] = { hH[jb], hH[jb+1], hH[jb+2], hH[jb+3] };
            #pragma unroll
            for (int j2 = 0; j2 < 4; j2++) {
                uint32_t bh[4];
                ldsm4(bh, wb + j2 * 4352 + kc * 32);
                float* c0 = &acc2[hf * 32 + (2*j2+0) * 4];
                float* c1 = &acc2[hf * 32 + (2*j2+1) * 4];
                mma16816(c0, ah, bh[0], bh[1]);
                mma16816(c1, ah, bh[2], bh[3]);
            }
        }
    }

    // ---- epilogue 2 ----
    {
        const int r0 = wr + (lane >> 2), r1 = r0 + 8;
        const int ec = 2 * (lane & 3);
        const int d0 = sDst[r0], d1 = sDst[r1];
        float* eo0 = ef_out + (size_t)(e0 + r0) * 64;
        float* eo1 = ef_out + (size_t)(e0 + r1) * 64;
        float* ag0 = g_agg + (size_t)d0 * 64;
        float* ag1 = g_agg + (size_t)d1 * 64;
        #pragma unroll
        for (int j8 = 0; j8 < 8; j8++) {
            int cb = j8 * 8 + ec;
            float be0 = sB2b[cb], be1v = sB2b[cb + 1];
            float ba0 = sB2b[64 + cb], ba1v = sB2b[64 + cb + 1];
            float ex0 = acc2[j8*4+0] + be0, ex1 = acc2[j8*4+1] + be1v;
            float ax0 = acc2[32 + j8*4+0] + ba0, ax1 = acc2[32 + j8*4+1] + ba1v;
            float m0 = ex0 / (1.f + __expf(-ax0));
            float m1 = ex1 / (1.f + __expf(-ax1));
            *(float2*)(eo0 + cb) = make_float2(m0, m1);
            red2(ag0 + cb, m0, m1);
            float ey0 = acc2[j8*4+2] + be0, ey1 = acc2[j8*4+3] + be1v;
            float ay0 = acc2[32 + j8*4+2] + ba0, ay1 = acc2[32 + j8*4+3] + ba1v;
            float n0 = ey0 / (1.f + __expf(-ay0));
            float n1 = ey1 / (1.f + __expf(-ay1));
            *(float2*)(eo1 + cb) = make_float2(n0, n1);
            red2(ag1 + cb, n0, n1);
        }
    }
}

// ---------------------------------------------------------------------------
// Node kernel (HMMA, f32-acc 3-term)
// ---------------------------------------------------------------------------
#define NOFF_B1  69632
#define NOFF_W2  139264
#define NOFF_MSC 174080
#define NODE_SMEM 174848

__global__ __launch_bounds__(256, 1) void node_kernel(
    const float* __restrict__ nf,
    const float* __restrict__ bn1, const float* __restrict__ bn2,
    float* __restrict__ nf_out)
{
    extern __shared__ char smc[];
    const uint32_t smb = smem_u32(smc);
    const int tid = threadIdx.x, wid = tid >> 5, lane = tid & 31;
    const int m0 = blockIdx.x * 128;
    float* sB1b = (float*)(smc + NOFF_MSC);
    float* sB2b = (float*)(smc + NOFF_MSC + 512);

    #pragma unroll
    for (int i = 0; i < 17; i++)
        cpa16(smb + NOFF_B1 + (tid + 256 * i) * 16, (const char*)g_Wn1 + (tid + 256 * i) * 16);
    #pragma unroll
    for (int i = 0; i < 9; i++) {
        int idx = tid + 256 * i;
        if (idx < 2176) cpa16(smb + NOFF_W2 + idx * 16, (const char*)g_Wn2 + idx * 16);
    }
    CP_COMMIT();

    if (tid < 32) ((float4*)sB1b)[tid] = ((const float4*)bn1)[tid];
    else if (tid < 48) ((float4*)sB2b)[tid - 32] = ((const float4*)bn2)[tid - 32];

    {
        const int m = tid >> 1, h = tid & 1;
        const int node = m0 + m;
        const float4* src = (h == 0) ? (const float4*)(g_agg + (size_t)node * 64)
                                     : (const float4*)(nf + (size_t)node * 64);
        #pragma unroll
        for (int it = 0; it < 16; it++) {
            float4 v = (node < NN) ? src[it] : make_float4(0.f, 0.f, 0.f, 0.f);
            int k = h * 64 + it * 4;
            uint32_t h0 = packh2(v.x, v.y), h1 = packh2(v.z, v.w);
            float2 f0 = unpackh2(h0), f1 = unpackh2(h1);
            uint32_t l0 = packh2(v.x - f0.x, v.y - f0.y), l1 = packh2(v.z - f1.x, v.w - f1.y);
            *(uint2*)(smc + 0     + m * 272 + k * 2) = make_uint2(h0, h1);
            *(uint2*)(smc + 34816 + m * 272 + k * 2) = make_uint2(l0, l1);
        }
    }
    CP_WAIT0();
    __syncthreads();

    const int wr = wid * 16;
    const uint32_t aH = smb + (uint32_t)((wr + (lane & 15)) * 272 + ((lane >> 4) * 8) * 2);
    const uint32_t aL = aH + 34816;
    const uint32_t bln = (uint32_t)((((lane >> 4) << 3) + (lane & 7)) * 272 + (((lane >> 3) & 1) ? 16 : 0));

    float acc[64];
    #pragma unroll
    for (int i = 0; i < 64; i++) acc[i] = 0.f;
    {
        const uint32_t bH = smb + NOFF_B1 + bln;
        const uint32_t bL = bH + 34816;
        #pragma unroll
        for (int ks = 0; ks < 8; ks++) {
            uint32_t ah[4], al[4];
            ldsm4(ah, aH + ks * 32);
            ldsm4(al, aL + ks * 32);
            #pragma unroll
            for (int j2 = 0; j2 < 8; j2++) {
                uint32_t bh[4], bl[4];
                ldsm4(bh, bH + j2 * 4352 + ks * 32);
                ldsm4(bl, bL + j2 * 4352 + ks * 32);
                float* c0 = &acc[(2*j2+0)*4];
                float* c1 = &acc[(2*j2+1)*4];
                mma16816(c0, ah, bh[0], bh[1]); mma16816(c1, ah, bh[2], bh[3]);
                mma16816(c0, al, bh[0], bh[1]); mma16816(c1, al, bh[2], bh[3]);
                mma16816(c0, ah, bl[0], bl[1]); mma16816(c1, ah, bl[2], bl[3]);
            }
        }
    }

    uint32_t hH[32], hL[32];
    {
        const int ec = 2 * (lane & 3);
        #pragma unroll
        for (int j8 = 0; j8 < 16; j8++) {
            int cb = 8 * j8 + ec;
            float b0 = sB1b[cb], b1 = sB1b[cb + 1];
            float v0 = fmaxf(acc[4*j8+0] + b0, 0.f);
            float v1 = fmaxf(acc[4*j8+1] + b1, 0.f);
            float v2 = fmaxf(acc[4*j8+2] + b0, 0.f);
            float v3 = fmaxf(acc[4*j8+3] + b1, 0.f);
            uint32_t h01 = packh2(v0, v1);
            float2 f01 = unpackh2(h01);
            uint32_t l01 = packh2(v0 - f01.x, v1 - f01.y);
            uint32_t h23 = packh2(v2, v3);
            float2 f23 = unpackh2(h23);
            uint32_t l23 = packh2(v2 - f23.x, v3 - f23.y);
            hH[2*j8] = h01; hL[2*j8] = l01;
            hH[2*j8+1] = h23; hL[2*j8+1] = l23;
        }
    }

    float acc2[32];
    #pragma unroll
    for (int i = 0; i < 32; i++) acc2[i] = 0.f;
    {
        const uint32_t wb = smb + NOFF_W2 + bln;
        #pragma unroll
        for (int kc = 0; kc < 8; kc++) {
            uint32_t ah[4] = { hH[4*kc], hH[4*kc+1], hH[4*kc+2], hH[4*kc+3] };
            uint32_t al[4] = { hL[4*kc], hL[4*kc+1], hL[4*kc+2], hL[4*kc+3] };
            #pragma unroll
            for (int j2 = 0; j2 < 4; j2++) {
                uint32_t bh[4], bl[4];
                ldsm4(bh, wb + j2 * 4352 + kc * 32);
                ldsm4(bl, wb + 17408 + j2 * 4352 + kc * 32);
                float* c0 = &acc2[(2*j2+0)*4];
                float* c1 = &acc2[(2*j2+1)*4];
                mma16816(c0, ah, bh[0], bh[1]); mma16816(c1, ah, bh[2], bh[3]);
                mma16816(c0, al, bh[0], bh[1]); mma16816(c1, al, bh[2], bh[3]);
                mma16816(c0, ah, bl[0], bl[1]); mma16816(c1, ah, bl[2], bl[3]);
            }
        }
    }

    {
        const int r0 = wr + (lane >> 2);
        const int ec = 2 * (lane & 3);
        const int n0 = m0 + r0, n1 = n0 + 8;
        #pragma unroll
        for (int j8 = 0; j8 < 8; j8++) {
            int cb = 8 * j8 + ec;
            float b0 = sB2b[cb], b1 = sB2b[cb + 1];
            if (n0 < NN)
                *(float2*)(nf_out + (size_t)n0 * 64 + cb) =
                    make_float2(acc2[4*j8+0] + b0, acc2[4*j8+1] + b1);
            if (n1 < NN)
                *(float2*)(nf_out + (size_t)n1 * 64 + cb) =
                    make_float2(acc2[4*j8+2] + b0, acc2[4*j8+3] + b1);
        }
    }
}

// ---------------------------------------------------------------------------
extern "C" void kernel_launch(void* const* d_in, const int* in_sizes, int n_in,
                              void* d_out, int out_size)
{
    const float* nf  = (const float*)d_in[0];
    const float* ef  = (const float*)d_in[1];
    const float* We1 = (const float*)d_in[4];
    const float* be1 = (const float*)d_in[5];
    const float* We2 = (const float*)d_in[6];
    const float* be2 = (const float*)d_in[7];
    const float* Wa1 = (const float*)d_in[8];
    const float* ba1 = (const float*)d_in[9];
    const float* Wa2 = (const float*)d_in[10];
    const float* ba2 = (const float*)d_in[11];
    const float* Wn1 = (const float*)d_in[12];
    const float* bn1 = (const float*)d_in[13];
    const float* Wn2 = (const float*)d_in[14];
    const float* bn2 = (const float*)d_in[15];

    float* nf_out = (float*)d_out;
    float* ef_out = nf_out + (size_t)NN * 64;

    cudaFuncSetAttribute(prep_P_kernel, cudaFuncAttributeMaxDynamicSharedMemorySize, PREP_SMEM);
    cudaFuncSetAttribute(edge_kernel, cudaFuncAttributeMaxDynamicSharedMemorySize, EDGE_SMEM);
    cudaFuncSetAttribute(node_kernel, cudaFuncAttributeMaxDynamicSharedMemorySize, NODE_SMEM);

    prep_all<<<3830, 256>>>((const unsigned int*)d_in[2], We1, Wa1, We2, Wa2, Wn1, Wn2);
    prep_P_kernel<<<391, 256, PREP_SMEM>>>(nf);
    edge_kernel<<<E_EDGES / 64, 128, EDGE_SMEM>>>(
        ef, (const int*)d_in[2], (const int*)d_in[3],
        be1, ba1, be2, ba2, ef_out);
    node_kernel<<<391, 256, NODE_SMEM>>>(nf, bn1, bn2, nf_out);
}